// round 3
// baseline (speedup 1.0000x reference)
#include <cuda_runtime.h>

#define S_  1024
#define D_  512
#define NH  8
#define DHD 64
#define CD  32768
#define NST 64
#define LCH 64
#define GCH 16

// ------------------- static device scratch (no runtime allocation) -------------------
__device__ float g_Q[S_*D_];
__device__ float g_K0[S_*D_];
__device__ float g_K[S_*D_];
__device__ float g_V[S_*D_];
__device__ float g_O1[S_*D_];
__device__ float g_dBre[NST], g_dBim[NST];
__device__ float g_pwre[(LCH+1)*NST];   // dA^p, p=0..64, layout [p][n]
__device__ float g_pwim[(LCH+1)*NST];
__device__ float g_CBre[NST*CD];        // (C_re + iC_im)*dB, transposed [n][c]
__device__ float g_CBim[NST*CD];
__device__ float g_Kds[LCH*CD];         // short SSM kernel [tau][c]
__device__ float g_U[S_*CD];            // KV signal [t][c]
__device__ float g_Y[S_*CD];            // SSM output [t][c]
__device__ float g_Zre[GCH*NST*CD];     // chunk sums -> overwritten with E
__device__ float g_Zim[GCH*NST*CD];

// ------------------- discretization + dA power table (double precision) -------------------
__global__ void k_tables(const float* __restrict__ A_re, const float* __restrict__ A_im){
    int n = threadIdx.x;
    if (n >= NST) return;
    double ar = (double)A_re[n], ai = (double)A_im[n];
    double hr = 1.0 + 0.05*ar, hi = 0.05*ai;    // 1 + dt/2*A
    double gr = 1.0 - 0.05*ar, gi = -0.05*ai;   // 1 - dt/2*A
    double den = gr*gr + gi*gi;
    double dAr = (hr*gr + hi*gi)/den;
    double dAi = (hi*gr - hr*gi)/den;
    g_dBre[n] = (float)( 0.1*gr/den);
    g_dBim[n] = (float)(-0.1*gi/den);
    double pr = 1.0, pi = 0.0;
    for (int p = 0; p <= LCH; p++){
        g_pwre[p*NST + n] = (float)pr;
        g_pwim[p*NST + n] = (float)pi;
        double nr = pr*dAr - pi*dAi;
        double ni = pr*dAi + pi*dAr;
        pr = nr; pi = ni;
    }
}

// ------------------- CB = (C_re + i C_im) * dB, transposed to [n][c] -------------------
__global__ void k_cb(const float* __restrict__ Cr, const float* __restrict__ Ci){
    int idx = blockIdx.x*256 + threadIdx.x;     // over CD*NST
    int n = idx & 63, c = idx >> 6;
    float dbr = g_dBre[n], dbi = g_dBim[n];
    float a = Cr[idx], b = Ci[idx];
    g_CBre[n*CD + c] = a*dbr - b*dbi;
    g_CBim[n*CD + c] = a*dbi + b*dbr;
}

// ------------------- Kds[tau][c] = 2*Re(sum_n CB[n,c]*dA^tau) -------------------
__global__ void __launch_bounds__(256) k_kds(){
    __shared__ float spr[NST*NST], spi[NST*NST];
    int tid = threadIdx.x;
    for (int i = tid; i < NST*NST; i += 256){ spr[i] = g_pwre[i]; spi[i] = g_pwim[i]; }
    __syncthreads();
    int c = blockIdx.x*256 + tid;
    float acc[LCH];
    #pragma unroll
    for (int t = 0; t < LCH; t++) acc[t] = 0.f;
    for (int n = 0; n < NST; n++){
        float cr = g_CBre[n*CD + c], ci = g_CBim[n*CD + c];
        #pragma unroll
        for (int t = 0; t < LCH; t++)
            acc[t] += cr*spr[t*NST + n] - ci*spi[t*NST + n];
    }
    #pragma unroll
    for (int t = 0; t < LCH; t++) g_Kds[t*CD + c] = 2.f*acc[t];
}

// ------------------- generic GEMM: C[M,N] = A[M,K] * B[N,K]^T -------------------
// 64x64 tile, 256 threads, 4x4 register blocking, K-tiles of 16.
__global__ void __launch_bounds__(256) k_gemm(const float* __restrict__ A,
                                              const float* __restrict__ B,
                                              float* __restrict__ C,
                                              int M, int N, int K){
    __shared__ float As[16][64], Bs[16][64];
    int m0 = blockIdx.y*64, n0 = blockIdx.x*64;
    int tid = threadIdx.x;
    int tx = tid & 15, ty = tid >> 4;
    int lr = tid >> 2, lc = (tid & 3)*4;
    float acc[4][4];
    #pragma unroll
    for (int i = 0; i < 4; i++)
        #pragma unroll
        for (int j = 0; j < 4; j++) acc[i][j] = 0.f;
    for (int k0 = 0; k0 < K; k0 += 16){
        float4 av = *(const float4*)&A[(m0+lr)*K + k0 + lc];
        float4 bv = *(const float4*)&B[(n0+lr)*K + k0 + lc];
        As[lc+0][lr] = av.x; As[lc+1][lr] = av.y; As[lc+2][lr] = av.z; As[lc+3][lr] = av.w;
        Bs[lc+0][lr] = bv.x; Bs[lc+1][lr] = bv.y; Bs[lc+2][lr] = bv.z; Bs[lc+3][lr] = bv.w;
        __syncthreads();
        #pragma unroll
        for (int kk = 0; kk < 16; kk++){
            float a[4], b[4];
            #pragma unroll
            for (int i = 0; i < 4; i++){ a[i] = As[kk][ty + 16*i]; b[i] = Bs[kk][tx + 16*i]; }
            #pragma unroll
            for (int i = 0; i < 4; i++)
                #pragma unroll
                for (int j = 0; j < 4; j++) acc[i][j] += a[i]*b[j];
        }
        __syncthreads();
    }
    #pragma unroll
    for (int i = 0; i < 4; i++)
        #pragma unroll
        for (int j = 0; j < 4; j++)
            C[(m0+ty+16*i)*N + n0+tx+16*j] = acc[i][j];
}

// ------------------- shift-SSM FIR on K -------------------
__global__ void k_shift(const float* __restrict__ Cs, const float* __restrict__ Ds){
    int idx = blockIdx.x*256 + threadIdx.x;     // over S_*D_
    int d = idx & (D_-1), t = idx >> 9;
    float acc = Ds[d]*g_K0[t*D_ + d];
    int jm = t < 63 ? t : 63;
    for (int j = 0; j <= jm; j++)
        acc += Cs[d*64 + j]*g_K0[(t-j)*D_ + d];
    g_K[idx] = acc;
}

// ------------------- U[t, h*4096 + i*64 + j] = K[t,h,i]*V[t,h,j] -------------------
__global__ void k_u(){
    int b = blockIdx.x; int h = b & 7, t = b >> 3;
    __shared__ float ks[64], vs[64];
    int tid = threadIdx.x;
    if (tid < 64)       ks[tid]    = g_K[t*D_ + h*64 + tid];
    else if (tid < 128) vs[tid-64] = g_V[t*D_ + h*64 + tid - 64];
    __syncthreads();
    float* Ur = g_U + t*CD + h*4096;
    for (int e = tid; e < 4096; e += 256)
        Ur[e] = ks[e >> 6]*vs[e & 63];
}

// ------------------- chunk summaries Z[g,n,c] = sum_p dA^{63-p} U[gL+p,c] -------------------
__global__ void __launch_bounds__(256) k_z(){
    __shared__ float Us[32][64];
    __shared__ float spr[NST][NST], spi[NST][NST];
    int c0 = blockIdx.x*64, g = blockIdx.y;
    int tid = threadIdx.x;
    int tx = tid & 15, ty = tid >> 4;
    for (int i = tid; i < NST*NST; i += 256){
        spr[i>>6][i&63] = g_pwre[i];
        spi[i>>6][i&63] = g_pwim[i];
    }
    float ar[4][4], ai[4][4];
    #pragma unroll
    for (int i = 0; i < 4; i++)
        #pragma unroll
        for (int j = 0; j < 4; j++){ ar[i][j] = 0.f; ai[i][j] = 0.f; }
    const float* Ub = g_U + (size_t)(g*64)*CD + c0;
    for (int half = 0; half < 2; half++){
        __syncthreads();
        for (int i = tid; i < 32*64; i += 256)
            Us[i>>6][i&63] = Ub[(size_t)(half*32 + (i>>6))*CD + (i&63)];
        __syncthreads();
        #pragma unroll 8
        for (int pp = 0; pp < 32; pp++){
            int p = half*32 + pp;
            float u[4], wr[4], wi[4];
            #pragma unroll
            for (int j = 0; j < 4; j++) u[j] = Us[pp][tx + 16*j];
            #pragma unroll
            for (int i = 0; i < 4; i++){
                wr[i] = spr[63-p][ty + 16*i];
                wi[i] = spi[63-p][ty + 16*i];
            }
            #pragma unroll
            for (int i = 0; i < 4; i++)
                #pragma unroll
                for (int j = 0; j < 4; j++){
                    ar[i][j] += wr[i]*u[j];
                    ai[i][j] += wi[i]*u[j];
                }
        }
    }
    #pragma unroll
    for (int i = 0; i < 4; i++)
        #pragma unroll
        for (int j = 0; j < 4; j++){
            size_t o = (size_t)(g*64 + ty + 16*i)*CD + c0 + tx + 16*j;
            g_Zre[o] = ar[i][j];
            g_Zim[o] = ai[i][j];
        }
}

// ------------------- inter-chunk scan; overwrite Z[g] with E[g] = 2*CB .* S_{g-1} -------------------
__global__ void k_scan(){
    size_t idx = (size_t)blockIdx.x*256 + threadIdx.x;   // over NST*CD
    int n = (int)(idx / CD);
    float cbr = g_CBre[idx], cbi = g_CBim[idx];
    float a64r = g_pwre[64*NST + n], a64i = g_pwim[64*NST + n];
    float sre = 0.f, sim = 0.f;
    for (int g = 0; g < GCH; g++){
        size_t o = (size_t)g*NST*CD + idx;
        float zr = g_Zre[o], zi = g_Zim[o];
        g_Zre[o] = 2.f*(cbr*sre - cbi*sim);
        g_Zim[o] = 2.f*(cbr*sim + cbi*sre);
        float nr = a64r*sre - a64i*sim + zr;
        float ni = a64r*sim + a64i*sre + zi;
        sre = nr; sim = ni;
    }
}

// ------------------- Y = intra-FIR + correction + skip -------------------
__global__ void __launch_bounds__(256) k_yfuse(const float* __restrict__ Dd){
    extern __shared__ float sm[];
    float (*Us)[64] = (float(*)[64])sm;
    float (*Kd)[64] = Us + 64;
    float (*Er)[64] = Kd + 64;
    float (*Ei)[64] = Er + 64;
    float (*Wr)[64] = Ei + 64;
    float (*Wi)[64] = Wr + 64;
    int c0 = blockIdx.x*64, g = blockIdx.y;
    int tid = threadIdx.x;
    int tx = tid & 15, ty = tid >> 4;
    for (int i = tid; i < 4096; i += 256){
        int r = i >> 6, c = i & 63;
        size_t o = (size_t)(g*64 + r)*CD + c0 + c;
        Us[r][c] = g_U[o];
        Kd[r][c] = g_Kds[(size_t)r*CD + c0 + c];
        Er[r][c] = g_Zre[o];
        Ei[r][c] = g_Zim[o];
        Wr[r][c] = g_pwre[(r+1)*NST + c];
        Wi[r][c] = g_pwim[(r+1)*NST + c];
    }
    __syncthreads();
    float acc[4][4];
    #pragma unroll
    for (int i = 0; i < 4; i++)
        #pragma unroll
        for (int j = 0; j < 4; j++) acc[i][j] = 0.f;
    // correction: sum_n Wr[p][n]*Er[n][c] - Wi[p][n]*Ei[n][c]   (2x folded in E)
    #pragma unroll 8
    for (int n = 0; n < NST; n++){
        float er[4], ei[4], wr[4], wi[4];
        #pragma unroll
        for (int j = 0; j < 4; j++){ er[j] = Er[n][tx + 16*j]; ei[j] = Ei[n][tx + 16*j]; }
        #pragma unroll
        for (int i = 0; i < 4; i++){ wr[i] = Wr[ty + 16*i][n]; wi[i] = Wi[ty + 16*i][n]; }
        #pragma unroll
        for (int i = 0; i < 4; i++)
            #pragma unroll
            for (int j = 0; j < 4; j++)
                acc[i][j] += wr[i]*er[j] - wi[i]*ei[j];
    }
    // intra-chunk FIR: sum_{tau<=p} Kds[tau][c]*U[p-tau][c]
    for (int tau = 0; tau < LCH; tau++){
        float kd[4];
        #pragma unroll
        for (int j = 0; j < 4; j++) kd[j] = Kd[tau][tx + 16*j];
        #pragma unroll
        for (int i = 0; i < 4; i++){
            int p = ty + 16*i;
            if (tau <= p){
                #pragma unroll
                for (int j = 0; j < 4; j++)
                    acc[i][j] += kd[j]*Us[p - tau][tx + 16*j];
            }
        }
    }
    #pragma unroll
    for (int i = 0; i < 4; i++)
        #pragma unroll
        for (int j = 0; j < 4; j++){
            int p = ty + 16*i, c = tx + 16*j;
            size_t o = (size_t)(g*64 + p)*CD + c0 + c;
            g_Y[o] = acc[i][j] + Dd[c0 + c]*Us[p][c];
        }
}

// ------------------- O[t,h,j] = sum_i Q[t,h,i]*Y[t, h*4096+i*64+j] -------------------
__global__ void k_o(){
    int t = blockIdx.x;
    int tid = threadIdx.x;   // 512
    int h = tid >> 6, j = tid & 63;
    __shared__ float qs[512];
    qs[tid] = g_Q[t*D_ + tid];
    __syncthreads();
    float acc = 0.f;
    const float* Yr = g_Y + (size_t)t*CD + h*4096 + j;
    #pragma unroll 8
    for (int i = 0; i < 64; i++)
        acc += qs[h*64 + i]*Yr[i*64];
    g_O1[t*D_ + tid] = acc;
}

// ------------------- launch -------------------
extern "C" void kernel_launch(void* const* d_in, const int* in_sizes, int n_in,
                              void* d_out, int out_size){
    const float* x  = (const float*)d_in[0];
    const float* WQ = (const float*)d_in[1];
    const float* WK = (const float*)d_in[2];
    const float* WV = (const float*)d_in[3];
    const float* WO = (const float*)d_in[4];
    const float* Cs = (const float*)d_in[5];
    const float* Ds = (const float*)d_in[6];
    const float* Ar = (const float*)d_in[7];
    const float* Ai = (const float*)d_in[8];
    const float* Cr = (const float*)d_in[9];
    const float* Ci = (const float*)d_in[10];
    const float* Dd = (const float*)d_in[11];
    float* out = (float*)d_out;

    float *pQ, *pK0, *pV, *pO1;
    cudaGetSymbolAddress((void**)&pQ,  g_Q);
    cudaGetSymbolAddress((void**)&pK0, g_K0);
    cudaGetSymbolAddress((void**)&pV,  g_V);
    cudaGetSymbolAddress((void**)&pO1, g_O1);

    k_tables<<<1, 64>>>(Ar, Ai);
    dim3 gg(D_/64, S_/64);
    k_gemm<<<gg, 256>>>(x, WQ, pQ,  S_, D_, D_);
    k_gemm<<<gg, 256>>>(x, WK, pK0, S_, D_, D_);
    k_gemm<<<gg, 256>>>(x, WV, pV,  S_, D_, D_);
    k_shift<<<(S_*D_)/256, 256>>>(Cs, Ds);
    k_cb<<<(CD*NST)/256, 256>>>(Cr, Ci);
    k_kds<<<CD/256, 256>>>();
    k_u<<<S_*NH, 256>>>();
    k_z<<<dim3(CD/64, GCH), 256>>>();
    k_scan<<<(NST*CD)/256, 256>>>();
    cudaFuncSetAttribute(k_yfuse, cudaFuncAttributeMaxDynamicSharedMemorySize, 6*64*64*4);
    k_yfuse<<<dim3(CD/64, GCH), 256, 6*64*64*4>>>(Dd);
    k_o<<<S_, 512>>>();
    k_gemm<<<gg, 256>>>(pO1, WO, out, S_, D_, D_);
}

// round 7
// speedup vs baseline: 1.1095x; 1.1095x over previous
#include <cuda_runtime.h>

#define S_  1024
#define D_  512
#define NH  8
#define DHD 64
#define CD  32768
#define NST 64
#define LCH 64
#define GCH 16

typedef unsigned long long u64_t;

__device__ __forceinline__ u64_t fma2(u64_t a, u64_t b, u64_t c){
    u64_t d; asm("fma.rn.f32x2 %0, %1, %2, %3;" : "=l"(d) : "l"(a), "l"(b), "l"(c)); return d;
}
__device__ __forceinline__ u64_t mul2(u64_t a, u64_t b){
    u64_t d; asm("mul.rn.f32x2 %0, %1, %2;" : "=l"(d) : "l"(a), "l"(b)); return d;
}
__device__ __forceinline__ u64_t pk2(float lo, float hi){
    u64_t r; asm("mov.b64 %0, {%1, %2};" : "=l"(r) : "f"(lo), "f"(hi)); return r;
}
__device__ __forceinline__ u64_t pks(float s){ return pk2(s, s); }
__device__ __forceinline__ float2 upk(u64_t a){
    float2 f; asm("mov.b64 {%0, %1}, %2;" : "=f"(f.x), "=f"(f.y) : "l"(a)); return f;
}

// ------------------- static device scratch -------------------
__device__ float g_Q[S_*D_];
__device__ float g_K0[S_*D_];
__device__ float g_K[S_*D_];
__device__ float g_V[S_*D_];
__device__ float g_O1[S_*D_];
__device__ float g_dBre[NST], g_dBim[NST];
__device__ float g_pwre[(LCH+1)*NST];   // dA^p, p=0..64, layout [p][n]
__device__ float g_pwim[(LCH+1)*NST];
__device__ float g_CBre[NST*CD];        // (C_re + iC_im)*dB, transposed [n][c]
__device__ float g_CBim[NST*CD];
__device__ float g_Kds[LCH*CD];         // short SSM kernel [tau][c]
__device__ float g_Y[S_*CD];            // SSM output [t][c]
__device__ float g_Zre[GCH*NST*CD];     // chunk sums -> overwritten with E
__device__ float g_Zim[GCH*NST*CD];

// ------------------- discretization + dA power table -------------------
__global__ void k_tables(const float* __restrict__ A_re, const float* __restrict__ A_im){
    int n = threadIdx.x;
    if (n >= NST) return;
    double ar = (double)A_re[n], ai = (double)A_im[n];
    double hr = 1.0 + 0.05*ar, hi = 0.05*ai;
    double gr = 1.0 - 0.05*ar, gi = -0.05*ai;
    double den = gr*gr + gi*gi;
    double dAr = (hr*gr + hi*gi)/den;
    double dAi = (hi*gr - hr*gi)/den;
    g_dBre[n] = (float)( 0.1*gr/den);
    g_dBim[n] = (float)(-0.1*gi/den);
    double pr = 1.0, pi = 0.0;
    for (int p = 0; p <= LCH; p++){
        g_pwre[p*NST + n] = (float)pr;
        g_pwim[p*NST + n] = (float)pi;
        double nr = pr*dAr - pi*dAi;
        double ni = pr*dAi + pi*dAr;
        pr = nr; pi = ni;
    }
}

// ------------------- CB = (C_re + i C_im)*dB, transposed to [n][c] -------------------
__global__ void k_cb(const float* __restrict__ Cr, const float* __restrict__ Ci){
    int idx = blockIdx.x*256 + threadIdx.x;
    int n = idx & 63, c = idx >> 6;
    float dbr = g_dBre[n], dbi = g_dBim[n];
    float a = Cr[idx], b = Ci[idx];
    g_CBre[n*CD + c] = a*dbr - b*dbi;
    g_CBim[n*CD + c] = a*dbi + b*dbr;
}

// ------------------- Kds[tau][c] = 2*Re(sum_n CB[n,c]*dA^tau) -------------------
__global__ void __launch_bounds__(256) k_kds(){
    __shared__ float spr[NST*NST], spi[NST*NST];
    int tid = threadIdx.x;
    for (int i = tid; i < NST*NST; i += 256){ spr[i] = g_pwre[i]; spi[i] = g_pwim[i]; }
    __syncthreads();
    int c = blockIdx.x*256 + tid;
    float acc[LCH];
    #pragma unroll
    for (int t = 0; t < LCH; t++) acc[t] = 0.f;
    for (int n = 0; n < NST; n++){
        float cr = g_CBre[n*CD + c], ci = g_CBim[n*CD + c];
        #pragma unroll
        for (int t = 0; t < LCH; t++)
            acc[t] += cr*spr[t*NST + n] - ci*spi[t*NST + n];
    }
    #pragma unroll
    for (int t = 0; t < LCH; t++) g_Kds[t*CD + c] = 2.f*acc[t];
}

// ------------------- merged QKV projections: grid.z selects W/output -------------------
__global__ void __launch_bounds__(256) k_qkv(const float* __restrict__ x,
                                             const float* __restrict__ WQ,
                                             const float* __restrict__ WK,
                                             const float* __restrict__ WV){
    const float* B = blockIdx.z == 0 ? WQ : (blockIdx.z == 1 ? WK : WV);
    float* C = blockIdx.z == 0 ? g_Q : (blockIdx.z == 1 ? g_K0 : g_V);
    __shared__ float As[16][64], Bs[16][64];
    int m0 = blockIdx.y*64, n0 = blockIdx.x*64;
    int tid = threadIdx.x;
    int tx = tid & 15, ty = tid >> 4;
    int lr = tid >> 2, lc = (tid & 3)*4;
    float acc[4][4];
    #pragma unroll
    for (int i = 0; i < 4; i++)
        #pragma unroll
        for (int j = 0; j < 4; j++) acc[i][j] = 0.f;
    for (int k0 = 0; k0 < D_; k0 += 16){
        float4 av = *(const float4*)&x[(m0+lr)*D_ + k0 + lc];
        float4 bv = *(const float4*)&B[(n0+lr)*D_ + k0 + lc];
        As[lc+0][lr] = av.x; As[lc+1][lr] = av.y; As[lc+2][lr] = av.z; As[lc+3][lr] = av.w;
        Bs[lc+0][lr] = bv.x; Bs[lc+1][lr] = bv.y; Bs[lc+2][lr] = bv.z; Bs[lc+3][lr] = bv.w;
        __syncthreads();
        #pragma unroll
        for (int kk = 0; kk < 16; kk++){
            float a[4], b[4];
            #pragma unroll
            for (int i = 0; i < 4; i++){ a[i] = As[kk][ty + 16*i]; b[i] = Bs[kk][tx + 16*i]; }
            #pragma unroll
            for (int i = 0; i < 4; i++)
                #pragma unroll
                for (int j = 0; j < 4; j++) acc[i][j] += a[i]*b[j];
        }
        __syncthreads();
    }
    #pragma unroll
    for (int i = 0; i < 4; i++)
        #pragma unroll
        for (int j = 0; j < 4; j++)
            C[(m0+ty+16*i)*D_ + n0+tx+16*j] = acc[i][j];
}

// ------------------- generic GEMM (final projection) -------------------
__global__ void __launch_bounds__(256) k_gemm(const float* __restrict__ A,
                                              const float* __restrict__ B,
                                              float* __restrict__ C,
                                              int M, int N, int K){
    __shared__ float As[16][64], Bs[16][64];
    int m0 = blockIdx.y*64, n0 = blockIdx.x*64;
    int tid = threadIdx.x;
    int tx = tid & 15, ty = tid >> 4;
    int lr = tid >> 2, lc = (tid & 3)*4;
    float acc[4][4];
    #pragma unroll
    for (int i = 0; i < 4; i++)
        #pragma unroll
        for (int j = 0; j < 4; j++) acc[i][j] = 0.f;
    for (int k0 = 0; k0 < K; k0 += 16){
        float4 av = *(const float4*)&A[(m0+lr)*K + k0 + lc];
        float4 bv = *(const float4*)&B[(n0+lr)*K + k0 + lc];
        As[lc+0][lr] = av.x; As[lc+1][lr] = av.y; As[lc+2][lr] = av.z; As[lc+3][lr] = av.w;
        Bs[lc+0][lr] = bv.x; Bs[lc+1][lr] = bv.y; Bs[lc+2][lr] = bv.z; Bs[lc+3][lr] = bv.w;
        __syncthreads();
        #pragma unroll
        for (int kk = 0; kk < 16; kk++){
            float a[4], b[4];
            #pragma unroll
            for (int i = 0; i < 4; i++){ a[i] = As[kk][ty + 16*i]; b[i] = Bs[kk][tx + 16*i]; }
            #pragma unroll
            for (int i = 0; i < 4; i++)
                #pragma unroll
                for (int j = 0; j < 4; j++) acc[i][j] += a[i]*b[j];
        }
        __syncthreads();
    }
    #pragma unroll
    for (int i = 0; i < 4; i++)
        #pragma unroll
        for (int j = 0; j < 4; j++)
            C[(m0+ty+16*i)*N + n0+tx+16*j] = acc[i][j];
}

// ------------------- shift-SSM FIR on K -------------------
__global__ void k_shift(const float* __restrict__ Cs, const float* __restrict__ Ds){
    int idx = blockIdx.x*256 + threadIdx.x;
    int d = idx & (D_-1), t = idx >> 9;
    float acc = Ds[d]*g_K0[t*D_ + d];
    int jm = t < 63 ? t : 63;
    for (int j = 0; j <= jm; j++)
        acc += Cs[d*64 + j]*g_K0[(t-j)*D_ + d];
    g_K[idx] = acc;
}

// ------------------- chunk summaries, fused U producer, f32x2 packed -------------------
// Z[g,n,c] = sum_p dA^{63-p} * K[g64+p, bx] * V[g64+p, vb + j]
__global__ void __launch_bounds__(256) k_z(){
    __shared__ float spr[64][64], spi[64][64];   // [p][n]
    __shared__ float Vs[32][64];
    __shared__ float Kc[64];
    int bx = blockIdx.x, g = blockIdx.y;
    int c0 = bx*64, vb = (bx >> 6)*64;
    int tid = threadIdx.x, tx = tid & 7, ty = tid >> 3;
    for (int i = tid; i < 4096; i += 256){ spr[i>>6][i&63] = g_pwre[i]; spi[i>>6][i&63] = g_pwim[i]; }
    if (tid < 64) Kc[tid] = g_K[(g*64 + tid)*D_ + bx];
    u64_t ar[2][4], ai[2][4];
    #pragma unroll
    for (int r = 0; r < 2; r++)
        #pragma unroll
        for (int q = 0; q < 4; q++){ ar[r][q] = 0ULL; ai[r][q] = 0ULL; }
    for (int half = 0; half < 2; half++){
        __syncthreads();
        for (int i = tid; i < 2048; i += 256)
            Vs[i>>6][i&63] = g_V[(size_t)(g*64 + half*32 + (i>>6))*D_ + vb + (i&63)];
        __syncthreads();
        #pragma unroll 4
        for (int pp = 0; pp < 32; pp++){
            int p = half*32 + pp;
            u64_t kp2 = pks(Kc[p]);
            float4 v0 = *(const float4*)&Vs[pp][8*tx];
            float4 v1 = *(const float4*)&Vs[pp][8*tx + 4];
            u64_t u[4];
            u[0] = mul2(kp2, pk2(v0.x, v0.y));
            u[1] = mul2(kp2, pk2(v0.z, v0.w));
            u[2] = mul2(kp2, pk2(v1.x, v1.y));
            u[3] = mul2(kp2, pk2(v1.z, v1.w));
            u64_t wr0 = pks(spr[63-p][ty]),    wr1 = pks(spr[63-p][ty+32]);
            u64_t wi0 = pks(spi[63-p][ty]),    wi1 = pks(spi[63-p][ty+32]);
            #pragma unroll
            for (int q = 0; q < 4; q++){
                ar[0][q] = fma2(wr0, u[q], ar[0][q]);
                ar[1][q] = fma2(wr1, u[q], ar[1][q]);
                ai[0][q] = fma2(wi0, u[q], ai[0][q]);
                ai[1][q] = fma2(wi1, u[q], ai[1][q]);
            }
        }
    }
    #pragma unroll
    for (int r = 0; r < 2; r++){
        int n = ty + 32*r;
        #pragma unroll
        for (int q = 0; q < 4; q++){
            size_t o = ((size_t)(g*64 + n))*CD + c0 + 8*tx + 2*q;
            *(float2*)&g_Zre[o] = upk(ar[r][q]);
            *(float2*)&g_Zim[o] = upk(ai[r][q]);
        }
    }
}

// ------------------- inter-chunk scan; overwrite Z[g] with E[g]=2*CB.*S_{g-1} -------------------
__global__ void k_scan(){
    size_t idx = (size_t)blockIdx.x*256 + threadIdx.x;   // over NST*CD
    int n = (int)(idx / CD);
    float cbr = g_CBre[idx], cbi = g_CBim[idx];
    float a64r = g_pwre[64*NST + n], a64i = g_pwim[64*NST + n];
    float sre = 0.f, sim = 0.f;
    for (int g = 0; g < GCH; g++){
        size_t o = (size_t)g*NST*CD + idx;
        float zr = g_Zre[o], zi = g_Zim[o];
        g_Zre[o] = 2.f*(cbr*sre - cbi*sim);
        g_Zim[o] = 2.f*(cbr*sim + cbi*sre);
        float nr = a64r*sre - a64i*sim + zr;
        float ni = a64r*sim + a64i*sre + zi;
        sre = nr; sim = ni;
    }
}

// ------------------- Y = intra-FIR + correction + skip, fused U, f32x2 packed -------------------
__global__ void __launch_bounds__(256) k_yfuse(const float* __restrict__ Dd){
    extern __shared__ float sm[];
    float (*Us)[64] = (float(*)[64])sm;   // [p][c]
    float (*Kd)[64] = Us + 64;            // [tau][c]
    float (*Er)[64] = Kd + 64;            // [n][c]
    float (*Ei)[64] = Er + 64;
    float (*Wr)[64] = Ei + 64;            // [p][n] = dA^{p+1}
    float (*Wi)[64] = Wr + 64;
    __shared__ float Kc[64];
    int bx = blockIdx.x, g = blockIdx.y;
    int c0 = bx*64, vb = (bx >> 6)*64;
    int tid = threadIdx.x, tx = tid & 7, ty = tid >> 3;
    if (tid < 64) Kc[tid] = g_K[(g*64 + tid)*D_ + bx];
    __syncthreads();
    for (int i = tid; i < 4096; i += 256){
        int r = i >> 6, c = i & 63;
        size_t o = ((size_t)(g*64 + r))*CD + c0 + c;
        Us[r][c] = Kc[r]*g_V[(size_t)(g*64 + r)*D_ + vb + c];
        Kd[r][c] = g_Kds[(size_t)r*CD + c0 + c];
        Er[r][c] = g_Zre[o];
        Ei[r][c] = g_Zim[o];
        Wr[r][c] = g_pwre[(r+1)*NST + c];
        Wi[r][c] = g_pwim[(r+1)*NST + c];
    }
    __syncthreads();
    u64_t acc[2][4];
    #pragma unroll
    for (int r = 0; r < 2; r++)
        #pragma unroll
        for (int q = 0; q < 4; q++) acc[r][q] = 0ULL;
    // correction: acc[p,c] += sum_n Wr[p][n]*Er[n][c] - Wi[p][n]*Ei[n][c]
    #pragma unroll 4
    for (int n = 0; n < 64; n++){
        float4 e0 = *(const float4*)&Er[n][8*tx];
        float4 e1 = *(const float4*)&Er[n][8*tx + 4];
        float4 f0 = *(const float4*)&Ei[n][8*tx];
        float4 f1 = *(const float4*)&Ei[n][8*tx + 4];
        u64_t er[4] = { pk2(e0.x,e0.y), pk2(e0.z,e0.w), pk2(e1.x,e1.y), pk2(e1.z,e1.w) };
        u64_t ei[4] = { pk2(f0.x,f0.y), pk2(f0.z,f0.w), pk2(f1.x,f1.y), pk2(f1.z,f1.w) };
        u64_t wr0 = pks(Wr[ty][n]),     wr1 = pks(Wr[ty+32][n]);
        u64_t wi0 = pks(-Wi[ty][n]),    wi1 = pks(-Wi[ty+32][n]);
        #pragma unroll
        for (int q = 0; q < 4; q++){
            acc[0][q] = fma2(wr0, er[q], acc[0][q]);
            acc[0][q] = fma2(wi0, ei[q], acc[0][q]);
            acc[1][q] = fma2(wr1, er[q], acc[1][q]);
            acc[1][q] = fma2(wi1, ei[q], acc[1][q]);
        }
    }
    // intra-chunk FIR: acc[p,c] += sum_{tau<=p} Kds[tau][c]*U[p-tau][c]
    int p0 = ty, p1 = ty + 32;
    #pragma unroll 2
    for (int tau = 0; tau < 64; tau++){
        float4 k0 = *(const float4*)&Kd[tau][8*tx];
        float4 k1 = *(const float4*)&Kd[tau][8*tx + 4];
        u64_t kd[4] = { pk2(k0.x,k0.y), pk2(k0.z,k0.w), pk2(k1.x,k1.y), pk2(k1.z,k1.w) };
        if (tau <= p0){
            float4 u0 = *(const float4*)&Us[p0 - tau][8*tx];
            float4 u1 = *(const float4*)&Us[p0 - tau][8*tx + 4];
            acc[0][0] = fma2(kd[0], pk2(u0.x,u0.y), acc[0][0]);
            acc[0][1] = fma2(kd[1], pk2(u0.z,u0.w), acc[0][1]);
            acc[0][2] = fma2(kd[2], pk2(u1.x,u1.y), acc[0][2]);
            acc[0][3] = fma2(kd[3], pk2(u1.z,u1.w), acc[0][3]);
        }
        if (tau <= p1){
            float4 u0 = *(const float4*)&Us[p1 - tau][8*tx];
            float4 u1 = *(const float4*)&Us[p1 - tau][8*tx + 4];
            acc[1][0] = fma2(kd[0], pk2(u0.x,u0.y), acc[1][0]);
            acc[1][1] = fma2(kd[1], pk2(u0.z,u0.w), acc[1][1]);
            acc[1][2] = fma2(kd[2], pk2(u1.x,u1.y), acc[1][2]);
            acc[1][3] = fma2(kd[3], pk2(u1.z,u1.w), acc[1][3]);
        }
    }
    // skip + store
    float4 d0 = *(const float4*)&Dd[c0 + 8*tx];
    float4 d1 = *(const float4*)&Dd[c0 + 8*tx + 4];
    u64_t dd[4] = { pk2(d0.x,d0.y), pk2(d0.z,d0.w), pk2(d1.x,d1.y), pk2(d1.z,d1.w) };
    #pragma unroll
    for (int r = 0; r < 2; r++){
        int p = ty + 32*r;
        float4 u0 = *(const float4*)&Us[p][8*tx];
        float4 u1 = *(const float4*)&Us[p][8*tx + 4];
        u64_t us[4] = { pk2(u0.x,u0.y), pk2(u0.z,u0.w), pk2(u1.x,u1.y), pk2(u1.z,u1.w) };
        #pragma unroll
        for (int q = 0; q < 4; q++){
            acc[r][q] = fma2(dd[q], us[q], acc[r][q]);
            size_t o = ((size_t)(g*64 + p))*CD + c0 + 8*tx + 2*q;
            *(float2*)&g_Y[o] = upk(acc[r][q]);
        }
    }
}

// ------------------- O[t,h,j] = sum_i Q[t,h,i]*Y[t, h*4096+i*64+j] -------------------
__global__ void k_o(){
    int t = blockIdx.x;
    int tid = threadIdx.x;   // 512
    int h = tid >> 6, j = tid & 63;
    __shared__ float qs[512];
    qs[tid] = g_Q[t*D_ + tid];
    __syncthreads();
    float acc = 0.f;
    const float* Yr = g_Y + (size_t)t*CD + h*4096 + j;
    #pragma unroll 8
    for (int i = 0; i < 64; i++)
        acc += qs[h*64 + i]*Yr[i*64];
    g_O1[t*D_ + tid] = acc;
}

// ------------------- launch -------------------
extern "C" void kernel_launch(void* const* d_in, const int* in_sizes, int n_in,
                              void* d_out, int out_size){
    const float* x  = (const float*)d_in[0];
    const float* WQ = (const float*)d_in[1];
    const float* WK = (const float*)d_in[2];
    const float* WV = (const float*)d_in[3];
    const float* WO = (const float*)d_in[4];
    const float* Cs = (const float*)d_in[5];
    const float* Ds = (const float*)d_in[6];
    const float* Ar = (const float*)d_in[7];
    const float* Ai = (const float*)d_in[8];
    const float* Cr = (const float*)d_in[9];
    const float* Ci = (const float*)d_in[10];
    const float* Dd = (const float*)d_in[11];
    float* out = (float*)d_out;

    float *pO1;
    cudaGetSymbolAddress((void**)&pO1, g_O1);

    k_tables<<<1, 64>>>(Ar, Ai);
    k_qkv<<<dim3(D_/64, S_/64, 3), 256>>>(x, WQ, WK, WV);
    k_shift<<<(S_*D_)/256, 256>>>(Cs, Ds);
    k_cb<<<(CD*NST)/256, 256>>>(Cr, Ci);
    k_kds<<<CD/256, 256>>>();
    k_z<<<dim3(CD/64, GCH), 256>>>();
    k_scan<<<(NST*CD)/256, 256>>>();
    cudaFuncSetAttribute(k_yfuse, cudaFuncAttributeMaxDynamicSharedMemorySize, 6*64*64*4);
    k_yfuse<<<dim3(CD/64, GCH), 256, 6*64*64*4>>>(Dd);
    k_o<<<S_, 512>>>();
    k_gemm<<<dim3(D_/64, S_/64), 256>>>(pO1, WO, out, S_, D_, D_);
}

// round 11
// speedup vs baseline: 2.2043x; 1.9868x over previous
#include <cuda_runtime.h>

#define S_  1024
#define D_  512
#define NH  8
#define DHD 64
#define CD  32768
#define NST 64
#define LCH 64
#define GCH 16

typedef unsigned long long u64_t;

__device__ __forceinline__ u64_t fma2(u64_t a, u64_t b, u64_t c){
    u64_t d; asm("fma.rn.f32x2 %0, %1, %2, %3;" : "=l"(d) : "l"(a), "l"(b), "l"(c)); return d;
}
__device__ __forceinline__ u64_t mul2(u64_t a, u64_t b){
    u64_t d; asm("mul.rn.f32x2 %0, %1, %2;" : "=l"(d) : "l"(a), "l"(b)); return d;
}
__device__ __forceinline__ u64_t pk2(float lo, float hi){
    u64_t r; asm("mov.b64 %0, {%1, %2};" : "=l"(r) : "f"(lo), "f"(hi)); return r;
}
__device__ __forceinline__ u64_t pks(float s){ return pk2(s, s); }
__device__ __forceinline__ float2 upk(u64_t a){
    float2 f; asm("mov.b64 {%0, %1}, %2;" : "=f"(f.x), "=f"(f.y) : "l"(a)); return f;
}

// ------------------- static device scratch -------------------
__device__ float g_Q[S_*D_];
__device__ float g_K0[S_*D_];
__device__ float g_K[S_*D_];
__device__ float g_V[S_*D_];
__device__ float g_O1[S_*D_];
__device__ float g_CsT[64*D_];          // transposed shift taps [j][d]
__device__ float g_dBre[NST], g_dBim[NST];
__device__ float g_pwre[(LCH+1)*NST];   // dA^p, p=0..64, layout [p][n]
__device__ float g_pwim[(LCH+1)*NST];
__device__ float g_CBre[NST*CD];        // (C_re + iC_im)*dB, transposed [n][c]
__device__ float g_CBim[NST*CD];
__device__ float g_Kds[LCH*CD];         // short SSM kernel [tau][c]
__device__ float g_Y[S_*CD];            // SSM output [t][c]

// ------------------- discretization + dA power table -------------------
__global__ void k_tables(const float* __restrict__ A_re, const float* __restrict__ A_im){
    int n = threadIdx.x;
    if (n >= NST) return;
    double ar = (double)A_re[n], ai = (double)A_im[n];
    double hr = 1.0 + 0.05*ar, hi = 0.05*ai;
    double gr = 1.0 - 0.05*ar, gi = -0.05*ai;
    double den = gr*gr + gi*gi;
    double dAr = (hr*gr + hi*gi)/den;
    double dAi = (hi*gr - hr*gi)/den;
    g_dBre[n] = (float)( 0.1*gr/den);
    g_dBim[n] = (float)(-0.1*gi/den);
    double pr = 1.0, pi = 0.0;
    for (int p = 0; p <= LCH; p++){
        g_pwre[p*NST + n] = (float)pr;
        g_pwim[p*NST + n] = (float)pi;
        double nr = pr*dAr - pi*dAi;
        double ni = pr*dAi + pi*dAr;
        pr = nr; pi = ni;
    }
}

// ------------------- CsT[j][d] = Cs[d][j] (tile transpose) -------------------
__global__ void __launch_bounds__(256) k_cst(const float* __restrict__ Cs){
    __shared__ float t[64][65];
    int d0 = blockIdx.x*64;
    int tid = threadIdx.x;
    for (int i = tid; i < 4096; i += 256){
        int dd = i >> 6, j = i & 63;
        t[dd][j] = Cs[(d0+dd)*64 + j];
    }
    __syncthreads();
    for (int i = tid; i < 4096; i += 256){
        int j = i >> 6, dd = i & 63;
        g_CsT[j*D_ + d0 + dd] = t[dd][j];
    }
}

// ------------------- CB = (C_re + i C_im)*dB, transposed via smem tile -------------------
__global__ void __launch_bounds__(256) k_cb(const float* __restrict__ Cr, const float* __restrict__ Ci){
    __shared__ float tr[64][65], ti[64][65];
    __shared__ float dbr[64], dbi[64];
    int c0 = blockIdx.x*64;
    int tid = threadIdx.x;
    if (tid < 64){ dbr[tid] = g_dBre[tid]; dbi[tid] = g_dBim[tid]; }
    __syncthreads();
    for (int i = tid; i < 4096; i += 256){
        int cc = i >> 6, nn = i & 63;
        float a = Cr[(c0+cc)*64 + nn], b = Ci[(c0+cc)*64 + nn];
        tr[cc][nn] = a*dbr[nn] - b*dbi[nn];
        ti[cc][nn] = a*dbi[nn] + b*dbr[nn];
    }
    __syncthreads();
    for (int i = tid; i < 4096; i += 256){
        int nn = i >> 6, cc = i & 63;
        g_CBre[(size_t)nn*CD + c0 + cc] = tr[cc][nn];
        g_CBim[(size_t)nn*CD + c0 + cc] = ti[cc][nn];
    }
}

// ------------------- Kds[tau][c] = 2*Re(sum_n CB[n,c]*dA^tau) -------------------
__global__ void __launch_bounds__(256) k_kds(){
    __shared__ float spr[NST*NST], spi[NST*NST];
    int tid = threadIdx.x;
    for (int i = tid; i < NST*NST; i += 256){ spr[i] = g_pwre[i]; spi[i] = g_pwim[i]; }
    __syncthreads();
    int c = blockIdx.x*256 + tid;
    float acc[LCH];
    #pragma unroll
    for (int t = 0; t < LCH; t++) acc[t] = 0.f;
    for (int n = 0; n < NST; n++){
        float cr = g_CBre[(size_t)n*CD + c], ci = g_CBim[(size_t)n*CD + c];
        #pragma unroll
        for (int t = 0; t < LCH; t++)
            acc[t] += cr*spr[t*NST + n] - ci*spi[t*NST + n];
    }
    #pragma unroll
    for (int t = 0; t < LCH; t++) g_Kds[(size_t)t*CD + c] = 2.f*acc[t];
}

// ------------------- merged QKV projections -------------------
__global__ void __launch_bounds__(256) k_qkv(const float* __restrict__ x,
                                             const float* __restrict__ WQ,
                                             const float* __restrict__ WK,
                                             const float* __restrict__ WV){
    const float* B = blockIdx.z == 0 ? WQ : (blockIdx.z == 1 ? WK : WV);
    float* C = blockIdx.z == 0 ? g_Q : (blockIdx.z == 1 ? g_K0 : g_V);
    __shared__ float As[16][64], Bs[16][64];
    int m0 = blockIdx.y*64, n0 = blockIdx.x*64;
    int tid = threadIdx.x;
    int tx = tid & 15, ty = tid >> 4;
    int lr = tid >> 2, lc = (tid & 3)*4;
    float acc[4][4];
    #pragma unroll
    for (int i = 0; i < 4; i++)
        #pragma unroll
        for (int j = 0; j < 4; j++) acc[i][j] = 0.f;
    for (int k0 = 0; k0 < D_; k0 += 16){
        float4 av = *(const float4*)&x[(m0+lr)*D_ + k0 + lc];
        float4 bv = *(const float4*)&B[(n0+lr)*D_ + k0 + lc];
        As[lc+0][lr] = av.x; As[lc+1][lr] = av.y; As[lc+2][lr] = av.z; As[lc+3][lr] = av.w;
        Bs[lc+0][lr] = bv.x; Bs[lc+1][lr] = bv.y; Bs[lc+2][lr] = bv.z; Bs[lc+3][lr] = bv.w;
        __syncthreads();
        #pragma unroll
        for (int kk = 0; kk < 16; kk++){
            float a[4], b[4];
            #pragma unroll
            for (int i = 0; i < 4; i++){ a[i] = As[kk][ty + 16*i]; b[i] = Bs[kk][tx + 16*i]; }
            #pragma unroll
            for (int i = 0; i < 4; i++)
                #pragma unroll
                for (int j = 0; j < 4; j++) acc[i][j] += a[i]*b[j];
        }
        __syncthreads();
    }
    #pragma unroll
    for (int i = 0; i < 4; i++)
        #pragma unroll
        for (int j = 0; j < 4; j++)
            C[(m0+ty+16*i)*D_ + n0+tx+16*j] = acc[i][j];
}

// ------------------- generic GEMM (final projection) -------------------
__global__ void __launch_bounds__(256) k_gemm(const float* __restrict__ A,
                                              const float* __restrict__ B,
                                              float* __restrict__ C,
                                              int M, int N, int K){
    __shared__ float As[16][64], Bs[16][64];
    int m0 = blockIdx.y*64, n0 = blockIdx.x*64;
    int tid = threadIdx.x;
    int tx = tid & 15, ty = tid >> 4;
    int lr = tid >> 2, lc = (tid & 3)*4;
    float acc[4][4];
    #pragma unroll
    for (int i = 0; i < 4; i++)
        #pragma unroll
        for (int j = 0; j < 4; j++) acc[i][j] = 0.f;
    for (int k0 = 0; k0 < K; k0 += 16){
        float4 av = *(const float4*)&A[(m0+lr)*K + k0 + lc];
        float4 bv = *(const float4*)&B[(n0+lr)*K + k0 + lc];
        As[lc+0][lr] = av.x; As[lc+1][lr] = av.y; As[lc+2][lr] = av.z; As[lc+3][lr] = av.w;
        Bs[lc+0][lr] = bv.x; Bs[lc+1][lr] = bv.y; Bs[lc+2][lr] = bv.z; Bs[lc+3][lr] = bv.w;
        __syncthreads();
        #pragma unroll
        for (int kk = 0; kk < 16; kk++){
            float a[4], b[4];
            #pragma unroll
            for (int i = 0; i < 4; i++){ a[i] = As[kk][ty + 16*i]; b[i] = Bs[kk][tx + 16*i]; }
            #pragma unroll
            for (int i = 0; i < 4; i++)
                #pragma unroll
                for (int j = 0; j < 4; j++) acc[i][j] += a[i]*b[j];
        }
        __syncthreads();
    }
    #pragma unroll
    for (int i = 0; i < 4; i++)
        #pragma unroll
        for (int j = 0; j < 4; j++)
            C[(m0+ty+16*i)*N + n0+tx+16*j] = acc[i][j];
}

// ------------------- shift-SSM FIR on K (coalesced taps via CsT) -------------------
__global__ void k_shift(const float* __restrict__ Ds){
    int idx = blockIdx.x*256 + threadIdx.x;
    int d = idx & (D_-1), t = idx >> 9;
    float acc = Ds[d]*g_K0[t*D_ + d];
    int jm = t < 63 ? t : 63;
    for (int j = 0; j <= jm; j++)
        acc += g_CsT[j*D_ + d]*g_K0[(t-j)*D_ + d];
    g_K[idx] = acc;
}

// ===================================================================
// k_big: fused U-producer + chunk summaries + inter-chunk scan (regs)
//        + E emission (smem) + correction GEMM + intra-FIR + skip.
// grid = CD/64 blocks; block walks all 16 chunks carrying SSM state.
// Thread tile: 4 channels (tx) x 2 rows (ty, ty+32) for p and n alike.
// ===================================================================
__global__ void __launch_bounds__(512) k_big(const float* __restrict__ Dd){
    extern __shared__ float sm[];
    float* spr = sm;             // [65][68]
    float* spi = sm + 4420;
    float* Us  = sm + 8840;      // [64][68]
    float* Er  = sm + 13192;     // [64][68]
    float* Ei  = sm + 17544;
    float* Kd  = sm + 21896;     // [64][68]
    int bx = blockIdx.x;
    int c0 = bx*64, vb = (bx >> 6)*64;
    int tid = threadIdx.x, tx = tid & 15, ty = tid >> 4;
    int n0 = ty, n1 = ty + 32;
    // tables (once per block)
    for (int i = tid; i < 65*64; i += 512){
        int r = i >> 6, n = i & 63;
        spr[r*68 + n] = g_pwre[i];
        spi[r*68 + n] = g_pwim[i];
    }
    for (int i = tid; i < 4096; i += 512){
        int r = i >> 6, c = i & 63;
        Kd[r*68 + c] = g_Kds[(size_t)r*CD + c0 + c];
    }
    // per-thread constants
    u64_t cb2r[2][2], cb2i[2][2], ncb2i[2][2];
    u64_t pa64r[2], pa64i[2], na64i[2];
    #pragma unroll
    for (int rn = 0; rn < 2; rn++){
        int n = ty + 32*rn;
        #pragma unroll
        for (int q = 0; q < 2; q++){
            float2 cr = *(const float2*)&g_CBre[(size_t)n*CD + c0 + 4*tx + 2*q];
            float2 ci = *(const float2*)&g_CBim[(size_t)n*CD + c0 + 4*tx + 2*q];
            cb2r[rn][q]  = pk2( 2.f*cr.x,  2.f*cr.y);
            cb2i[rn][q]  = pk2( 2.f*ci.x,  2.f*ci.y);
            ncb2i[rn][q] = pk2(-2.f*ci.x, -2.f*ci.y);
        }
        float a64r = g_pwre[64*NST + n], a64i = g_pwim[64*NST + n];
        pa64r[rn] = pks(a64r); pa64i[rn] = pks(a64i); na64i[rn] = pks(-a64i);
    }
    float4 dv = *(const float4*)&Dd[c0 + 4*tx];
    u64_t dd0 = pk2(dv.x, dv.y), dd1 = pk2(dv.z, dv.w);
    u64_t sre[2][2] = {0ULL,0ULL,0ULL,0ULL}, smi[2][2] = {0ULL,0ULL,0ULL,0ULL};

    for (int g = 0; g < GCH; g++){
        int tbase = g*64;
        __syncthreads();   // protect Us/Er/Ei reuse from previous chunk's consumers
        // U tile (fused K (x) V) into smem
        for (int i = tid; i < 4096; i += 512){
            int r = i >> 6, c = i & 63;
            float kv = g_K[(size_t)(tbase+r)*D_ + bx];
            Us[r*68 + c] = kv * g_V[(size_t)(tbase+r)*D_ + vb + c];
        }
        // E = 2*CB .* S_prev  -> smem
        #pragma unroll
        for (int rn = 0; rn < 2; rn++){
            int n = ty + 32*rn;
            u64_t e0 = fma2(cb2r[rn][0], sre[rn][0], mul2(ncb2i[rn][0], smi[rn][0]));
            u64_t e1 = fma2(cb2r[rn][1], sre[rn][1], mul2(ncb2i[rn][1], smi[rn][1]));
            u64_t f0 = fma2(cb2r[rn][0], smi[rn][0], mul2(cb2i[rn][0], sre[rn][0]));
            u64_t f1 = fma2(cb2r[rn][1], smi[rn][1], mul2(cb2i[rn][1], sre[rn][1]));
            float2 a = upk(e0), b = upk(e1);
            *(float4*)&Er[n*68 + 4*tx] = make_float4(a.x, a.y, b.x, b.y);
            a = upk(f0); b = upk(f1);
            *(float4*)&Ei[n*68 + 4*tx] = make_float4(a.x, a.y, b.x, b.y);
        }
        __syncthreads();
        // Z[n,c] = sum_p dA^{63-p} * U[p,c]
        u64_t zr[2][2] = {0ULL,0ULL,0ULL,0ULL}, zi[2][2] = {0ULL,0ULL,0ULL,0ULL};
        #pragma unroll 4
        for (int p = 0; p < 64; p++){
            float4 u = *(const float4*)&Us[p*68 + 4*tx];
            u64_t u0 = pk2(u.x, u.y), u1 = pk2(u.z, u.w);
            int row = (63-p)*68;
            u64_t wr0 = pks(spr[row + n0]), wr1 = pks(spr[row + n1]);
            u64_t wi0 = pks(spi[row + n0]), wi1 = pks(spi[row + n1]);
            zr[0][0] = fma2(wr0,u0,zr[0][0]); zr[0][1] = fma2(wr0,u1,zr[0][1]);
            zr[1][0] = fma2(wr1,u0,zr[1][0]); zr[1][1] = fma2(wr1,u1,zr[1][1]);
            zi[0][0] = fma2(wi0,u0,zi[0][0]); zi[0][1] = fma2(wi0,u1,zi[0][1]);
            zi[1][0] = fma2(wi1,u0,zi[1][0]); zi[1][1] = fma2(wi1,u1,zi[1][1]);
        }
        // S = dA^64 * S + Z
        #pragma unroll
        for (int rn = 0; rn < 2; rn++)
            #pragma unroll
            for (int q = 0; q < 2; q++){
                u64_t nr = fma2(pa64r[rn], sre[rn][q], fma2(na64i[rn], smi[rn][q], zr[rn][q]));
                u64_t ni = fma2(pa64r[rn], smi[rn][q], fma2(pa64i[rn], sre[rn][q], zi[rn][q]));
                sre[rn][q] = nr; smi[rn][q] = ni;
            }
        // Y = corr + FIR + skip
        u64_t accA[2][2] = {0ULL,0ULL,0ULL,0ULL}, accB[2][2] = {0ULL,0ULL,0ULL,0ULL};
        int rw0 = (ty+1)*68, rw1 = (ty+33)*68;
        #pragma unroll 4
        for (int n = 0; n < 64; n++){
            float4 e = *(const float4*)&Er[n*68 + 4*tx];
            float4 f = *(const float4*)&Ei[n*68 + 4*tx];
            u64_t e0 = pk2(e.x,e.y), e1 = pk2(e.z,e.w);
            u64_t f0 = pk2(f.x,f.y), f1 = pk2(f.z,f.w);
            u64_t wr0 = pks(spr[rw0 + n]), wr1 = pks(spr[rw1 + n]);
            u64_t wi0 = pks(spi[rw0 + n]), wi1 = pks(spi[rw1 + n]);
            accA[0][0] = fma2(wr0,e0,accA[0][0]); accA[0][1] = fma2(wr0,e1,accA[0][1]);
            accA[1][0] = fma2(wr1,e0,accA[1][0]); accA[1][1] = fma2(wr1,e1,accA[1][1]);
            accB[0][0] = fma2(wi0,f0,accB[0][0]); accB[0][1] = fma2(wi0,f1,accB[0][1]);
            accB[1][0] = fma2(wi1,f0,accB[1][0]); accB[1][1] = fma2(wi1,f1,accB[1][1]);
        }
        int p0 = ty, p1 = ty + 32;
        #pragma unroll 2
        for (int tau = 0; tau < 64; tau++){
            float4 kdv = *(const float4*)&Kd[tau*68 + 4*tx];
            u64_t k0 = pk2(kdv.x,kdv.y), k1 = pk2(kdv.z,kdv.w);
            if (tau <= p0){
                float4 u = *(const float4*)&Us[(p0-tau)*68 + 4*tx];
                accA[0][0] = fma2(k0, pk2(u.x,u.y), accA[0][0]);
                accA[0][1] = fma2(k1, pk2(u.z,u.w), accA[0][1]);
            }
            if (tau <= p1){
                float4 u = *(const float4*)&Us[(p1-tau)*68 + 4*tx];
                accA[1][0] = fma2(k0, pk2(u.x,u.y), accA[1][0]);
                accA[1][1] = fma2(k1, pk2(u.z,u.w), accA[1][1]);
            }
        }
        #pragma unroll
        for (int r = 0; r < 2; r++){
            int p = ty + 32*r;
            float4 u = *(const float4*)&Us[p*68 + 4*tx];
            accA[r][0] = fma2(dd0, pk2(u.x,u.y), accA[r][0]);
            accA[r][1] = fma2(dd1, pk2(u.z,u.w), accA[r][1]);
            float2 a0 = upk(accA[r][0]), b0 = upk(accB[r][0]);
            float2 a1 = upk(accA[r][1]), b1 = upk(accB[r][1]);
            *(float4*)&g_Y[(size_t)(tbase+p)*CD + c0 + 4*tx] =
                make_float4(a0.x-b0.x, a0.y-b0.y, a1.x-b1.x, a1.y-b1.y);
        }
    }
}

// ------------------- O[t,h,j] = sum_i Q[t,h,i]*Y[t, h*4096+i*64+j] -------------------
__global__ void k_o(){
    int t = blockIdx.x;
    int tid = threadIdx.x;   // 512
    int h = tid >> 6, j = tid & 63;
    __shared__ float qs[512];
    qs[tid] = g_Q[t*D_ + tid];
    __syncthreads();
    float acc = 0.f;
    const float* Yr = g_Y + (size_t)t*CD + h*4096 + j;
    #pragma unroll 8
    for (int i = 0; i < 64; i++)
        acc += qs[h*64 + i]*Yr[i*64];
    g_O1[t*D_ + tid] = acc;
}

// ------------------- launch -------------------
extern "C" void kernel_launch(void* const* d_in, const int* in_sizes, int n_in,
                              void* d_out, int out_size){
    const float* x  = (const float*)d_in[0];
    const float* WQ = (const float*)d_in[1];
    const float* WK = (const float*)d_in[2];
    const float* WV = (const float*)d_in[3];
    const float* WO = (const float*)d_in[4];
    const float* Cs = (const float*)d_in[5];
    const float* Ds = (const float*)d_in[6];
    const float* Ar = (const float*)d_in[7];
    const float* Ai = (const float*)d_in[8];
    const float* Cr = (const float*)d_in[9];
    const float* Ci = (const float*)d_in[10];
    const float* Dd = (const float*)d_in[11];
    float* out = (float*)d_out;

    float *pO1;
    cudaGetSymbolAddress((void**)&pO1, g_O1);

    const int BIG_SMEM = 26248*4;
    cudaFuncSetAttribute(k_big, cudaFuncAttributeMaxDynamicSharedMemorySize, BIG_SMEM);

    k_tables<<<1, 64>>>(Ar, Ai);
    k_cst<<<D_/64, 256>>>(Cs);
    k_qkv<<<dim3(D_/64, S_/64, 3), 256>>>(x, WQ, WK, WV);
    k_shift<<<(S_*D_)/256, 256>>>(Ds);
    k_cb<<<CD/64, 256>>>(Cr, Ci);
    k_kds<<<CD/256, 256>>>();
    k_big<<<CD/64, 512, BIG_SMEM>>>(Dd);
    k_o<<<S_, 512>>>();
    k_gemm<<<dim3(D_/64, S_/64), 256>>>(pO1, WO, out, S_, D_, D_);
}

// round 14
// speedup vs baseline: 2.2060x; 1.0008x over previous
#include <cuda_runtime.h>

#define S_  1024
#define D_  512
#define NH  8
#define DHD 64
#define CD  32768
#define NST 64
#define LCH 64
#define GCH 16

typedef unsigned long long u64_t;

__device__ __forceinline__ u64_t fma2(u64_t a, u64_t b, u64_t c){
    u64_t d; asm("fma.rn.f32x2 %0, %1, %2, %3;" : "=l"(d) : "l"(a), "l"(b), "l"(c)); return d;
}
__device__ __forceinline__ u64_t mul2(u64_t a, u64_t b){
    u64_t d; asm("mul.rn.f32x2 %0, %1, %2;" : "=l"(d) : "l"(a), "l"(b)); return d;
}
__device__ __forceinline__ u64_t pk2(float lo, float hi){
    u64_t r; asm("mov.b64 %0, {%1, %2};" : "=l"(r) : "f"(lo), "f"(hi)); return r;
}
__device__ __forceinline__ u64_t pks(float s){ return pk2(s, s); }
__device__ __forceinline__ float2 upk(u64_t a){
    float2 f; asm("mov.b64 {%0, %1}, %2;" : "=f"(f.x), "=f"(f.y) : "l"(a)); return f;
}

// ------------------- static device scratch -------------------
__device__ float g_Q[S_*D_];
__device__ float g_K0[S_*D_];
__device__ float g_K[S_*D_];
__device__ float g_V[S_*D_];
__device__ float g_O1[S_*D_];
__device__ float g_CsT[64*D_];          // transposed shift taps [j][d]
__device__ float g_dBre[NST], g_dBim[NST];
__device__ float g_pwre[(LCH+1)*NST];   // dA^p, p=0..64, layout [p][n]
__device__ float g_pwim[(LCH+1)*NST];
__device__ float g_CBre[NST*CD];        // (C_re + iC_im)*dB, transposed [n][c]
__device__ float g_CBim[NST*CD];
__device__ float g_Kds[LCH*CD];         // short SSM kernel [tau][c]
__device__ float g_Y[S_*CD];            // SSM output [t][c]

// ------------------- discretization + dA power table -------------------
__global__ void k_tables(const float* __restrict__ A_re, const float* __restrict__ A_im){
    int n = threadIdx.x;
    if (n >= NST) return;
    double ar = (double)A_re[n], ai = (double)A_im[n];
    double hr = 1.0 + 0.05*ar, hi = 0.05*ai;
    double gr = 1.0 - 0.05*ar, gi = -0.05*ai;
    double den = gr*gr + gi*gi;
    double dAr = (hr*gr + hi*gi)/den;
    double dAi = (hi*gr - hr*gi)/den;
    g_dBre[n] = (float)( 0.1*gr/den);
    g_dBim[n] = (float)(-0.1*gi/den);
    double pr = 1.0, pi = 0.0;
    for (int p = 0; p <= LCH; p++){
        g_pwre[p*NST + n] = (float)pr;
        g_pwim[p*NST + n] = (float)pi;
        double nr = pr*dAr - pi*dAi;
        double ni = pr*dAi + pi*dAr;
        pr = nr; pi = ni;
    }
}

// ------------------- CsT[j][d] = Cs[d][j] (tile transpose) -------------------
__global__ void __launch_bounds__(256) k_cst(const float* __restrict__ Cs){
    __shared__ float t[64][65];
    int d0 = blockIdx.x*64;
    int tid = threadIdx.x;
    for (int i = tid; i < 4096; i += 256){
        int dd = i >> 6, j = i & 63;
        t[dd][j] = Cs[(d0+dd)*64 + j];
    }
    __syncthreads();
    for (int i = tid; i < 4096; i += 256){
        int j = i >> 6, dd = i & 63;
        g_CsT[j*D_ + d0 + dd] = t[dd][j];
    }
}

// ------------------- CB = (C_re + i C_im)*dB, transposed via smem tile -------------------
__global__ void __launch_bounds__(256) k_cb(const float* __restrict__ Cr, const float* __restrict__ Ci){
    __shared__ float tr[64][65], ti[64][65];
    __shared__ float dbr[64], dbi[64];
    int c0 = blockIdx.x*64;
    int tid = threadIdx.x;
    if (tid < 64){ dbr[tid] = g_dBre[tid]; dbi[tid] = g_dBim[tid]; }
    __syncthreads();
    for (int i = tid; i < 4096; i += 256){
        int cc = i >> 6, nn = i & 63;
        float a = Cr[(c0+cc)*64 + nn], b = Ci[(c0+cc)*64 + nn];
        tr[cc][nn] = a*dbr[nn] - b*dbi[nn];
        ti[cc][nn] = a*dbi[nn] + b*dbr[nn];
    }
    __syncthreads();
    for (int i = tid; i < 4096; i += 256){
        int nn = i >> 6, cc = i & 63;
        g_CBre[(size_t)nn*CD + c0 + cc] = tr[cc][nn];
        g_CBim[(size_t)nn*CD + c0 + cc] = ti[cc][nn];
    }
}

// ------------------- Kds[tau][c] = 2*Re(sum_n CB[n,c]*dA^tau) -------------------
__global__ void __launch_bounds__(256) k_kds(){
    __shared__ float spr[NST*NST], spi[NST*NST];
    int tid = threadIdx.x;
    for (int i = tid; i < NST*NST; i += 256){ spr[i] = g_pwre[i]; spi[i] = g_pwim[i]; }
    __syncthreads();
    int c = blockIdx.x*256 + tid;
    float acc[LCH];
    #pragma unroll
    for (int t = 0; t < LCH; t++) acc[t] = 0.f;
    for (int n = 0; n < NST; n++){
        float cr = g_CBre[(size_t)n*CD + c], ci = g_CBim[(size_t)n*CD + c];
        #pragma unroll
        for (int t = 0; t < LCH; t++)
            acc[t] += cr*spr[t*NST + n] - ci*spi[t*NST + n];
    }
    #pragma unroll
    for (int t = 0; t < LCH; t++) g_Kds[(size_t)t*CD + c] = 2.f*acc[t];
}

// ------------------- merged QKV projections -------------------
__global__ void __launch_bounds__(256) k_qkv(const float* __restrict__ x,
                                             const float* __restrict__ WQ,
                                             const float* __restrict__ WK,
                                             const float* __restrict__ WV){
    const float* B = blockIdx.z == 0 ? WQ : (blockIdx.z == 1 ? WK : WV);
    float* C = blockIdx.z == 0 ? g_Q : (blockIdx.z == 1 ? g_K0 : g_V);
    __shared__ float As[16][64], Bs[16][64];
    int m0 = blockIdx.y*64, n0 = blockIdx.x*64;
    int tid = threadIdx.x;
    int tx = tid & 15, ty = tid >> 4;
    int lr = tid >> 2, lc = (tid & 3)*4;
    float acc[4][4];
    #pragma unroll
    for (int i = 0; i < 4; i++)
        #pragma unroll
        for (int j = 0; j < 4; j++) acc[i][j] = 0.f;
    for (int k0 = 0; k0 < D_; k0 += 16){
        float4 av = *(const float4*)&x[(m0+lr)*D_ + k0 + lc];
        float4 bv = *(const float4*)&B[(n0+lr)*D_ + k0 + lc];
        As[lc+0][lr] = av.x; As[lc+1][lr] = av.y; As[lc+2][lr] = av.z; As[lc+3][lr] = av.w;
        Bs[lc+0][lr] = bv.x; Bs[lc+1][lr] = bv.y; Bs[lc+2][lr] = bv.z; Bs[lc+3][lr] = bv.w;
        __syncthreads();
        #pragma unroll
        for (int kk = 0; kk < 16; kk++){
            float a[4], b[4];
            #pragma unroll
            for (int i = 0; i < 4; i++){ a[i] = As[kk][ty + 16*i]; b[i] = Bs[kk][tx + 16*i]; }
            #pragma unroll
            for (int i = 0; i < 4; i++)
                #pragma unroll
                for (int j = 0; j < 4; j++) acc[i][j] += a[i]*b[j];
        }
        __syncthreads();
    }
    #pragma unroll
    for (int i = 0; i < 4; i++)
        #pragma unroll
        for (int j = 0; j < 4; j++)
            C[(m0+ty+16*i)*D_ + n0+tx+16*j] = acc[i][j];
}

// ------------------- generic GEMM (final projection) -------------------
__global__ void __launch_bounds__(256) k_gemm(const float* __restrict__ A,
                                              const float* __restrict__ B,
                                              float* __restrict__ C,
                                              int M, int N, int K){
    __shared__ float As[16][64], Bs[16][64];
    int m0 = blockIdx.y*64, n0 = blockIdx.x*64;
    int tid = threadIdx.x;
    int tx = tid & 15, ty = tid >> 4;
    int lr = tid >> 2, lc = (tid & 3)*4;
    float acc[4][4];
    #pragma unroll
    for (int i = 0; i < 4; i++)
        #pragma unroll
        for (int j = 0; j < 4; j++) acc[i][j] = 0.f;
    for (int k0 = 0; k0 < K; k0 += 16){
        float4 av = *(const float4*)&A[(m0+lr)*K + k0 + lc];
        float4 bv = *(const float4*)&B[(n0+lr)*K + k0 + lc];
        As[lc+0][lr] = av.x; As[lc+1][lr] = av.y; As[lc+2][lr] = av.z; As[lc+3][lr] = av.w;
        Bs[lc+0][lr] = bv.x; Bs[lc+1][lr] = bv.y; Bs[lc+2][lr] = bv.z; Bs[lc+3][lr] = bv.w;
        __syncthreads();
        #pragma unroll
        for (int kk = 0; kk < 16; kk++){
            float a[4], b[4];
            #pragma unroll
            for (int i = 0; i < 4; i++){ a[i] = As[kk][ty + 16*i]; b[i] = Bs[kk][tx + 16*i]; }
            #pragma unroll
            for (int i = 0; i < 4; i++)
                #pragma unroll
                for (int j = 0; j < 4; j++) acc[i][j] += a[i]*b[j];
        }
        __syncthreads();
    }
    #pragma unroll
    for (int i = 0; i < 4; i++)
        #pragma unroll
        for (int j = 0; j < 4; j++)
            C[(m0+ty+16*i)*N + n0+tx+16*j] = acc[i][j];
}

// ------------------- shift-SSM FIR on K (coalesced taps via CsT) -------------------
__global__ void k_shift(const float* __restrict__ Ds){
    int idx = blockIdx.x*256 + threadIdx.x;
    int d = idx & (D_-1), t = idx >> 9;
    float acc = Ds[d]*g_K0[t*D_ + d];
    int jm = t < 63 ? t : 63;
    for (int j = 0; j <= jm; j++)
        acc += g_CsT[j*D_ + d]*g_K0[(t-j)*D_ + d];
    g_K[idx] = acc;
}

// ===================================================================
// k_big: fused U-producer + chunk summaries + inter-chunk scan (regs)
//        + E emission (smem) + correction GEMM + intra-FIR + skip.
// grid = CD/64 blocks; block walks all 16 chunks carrying SSM state.
// Thread tile: 4 channels (tx) x 2 rows (ty, ty+32) for p and n alike.
// ===================================================================
__global__ void __launch_bounds__(512) k_big(const float* __restrict__ Dd){
    extern __shared__ float sm[];
    float* spr = sm;             // [65][68]
    float* spi = sm + 4420;
    float* Us  = sm + 8840;      // [64][68]
    float* Er  = sm + 13192;     // [64][68]
    float* Ei  = sm + 17544;
    float* Kd  = sm + 21896;     // [64][68]
    int bx = blockIdx.x;
    int c0 = bx*64, vb = (bx >> 6)*64;
    int tid = threadIdx.x, tx = tid & 15, ty = tid >> 4;
    int n0 = ty, n1 = ty + 32;
    // tables (once per block)
    for (int i = tid; i < 65*64; i += 512){
        int r = i >> 6, n = i & 63;
        spr[r*68 + n] = g_pwre[i];
        spi[r*68 + n] = g_pwim[i];
    }
    for (int i = tid; i < 4096; i += 512){
        int r = i >> 6, c = i & 63;
        Kd[r*68 + c] = g_Kds[(size_t)r*CD + c0 + c];
    }
    // per-thread constants
    u64_t cb2r[2][2], cb2i[2][2], ncb2i[2][2];
    u64_t pa64r[2], pa64i[2], na64i[2];
    #pragma unroll
    for (int rn = 0; rn < 2; rn++){
        int n = ty + 32*rn;
        #pragma unroll
        for (int q = 0; q < 2; q++){
            float2 cr = *(const float2*)&g_CBre[(size_t)n*CD + c0 + 4*tx + 2*q];
            float2 ci = *(const float2*)&g_CBim[(size_t)n*CD + c0 + 4*tx + 2*q];
            cb2r[rn][q]  = pk2( 2.f*cr.x,  2.f*cr.y);
            cb2i[rn][q]  = pk2( 2.f*ci.x,  2.f*ci.y);
            ncb2i[rn][q] = pk2(-2.f*ci.x, -2.f*ci.y);
        }
        float a64r = g_pwre[64*NST + n], a64i = g_pwim[64*NST + n];
        pa64r[rn] = pks(a64r); pa64i[rn] = pks(a64i); na64i[rn] = pks(-a64i);
    }
    float4 dv = *(const float4*)&Dd[c0 + 4*tx];
    u64_t dd0 = pk2(dv.x, dv.y), dd1 = pk2(dv.z, dv.w);
    u64_t sre[2][2] = {0ULL,0ULL,0ULL,0ULL}, smi[2][2] = {0ULL,0ULL,0ULL,0ULL};

    for (int g = 0; g < GCH; g++){
        int tbase = g*64;
        __syncthreads();   // protect Us/Er/Ei reuse from previous chunk's consumers
        // U tile (fused K (x) V) into smem
        for (int i = tid; i < 4096; i += 512){
            int r = i >> 6, c = i & 63;
            float kv = g_K[(size_t)(tbase+r)*D_ + bx];
            Us[r*68 + c] = kv * g_V[(size_t)(tbase+r)*D_ + vb + c];
        }
        // E = 2*CB .* S_prev  -> smem
        #pragma unroll
        for (int rn = 0; rn < 2; rn++){
            int n = ty + 32*rn;
            u64_t e0 = fma2(cb2r[rn][0], sre[rn][0], mul2(ncb2i[rn][0], smi[rn][0]));
            u64_t e1 = fma2(cb2r[rn][1], sre[rn][1], mul2(ncb2i[rn][1], smi[rn][1]));
            u64_t f0 = fma2(cb2r[rn][0], smi[rn][0], mul2(cb2i[rn][0], sre[rn][0]));
            u64_t f1 = fma2(cb2r[rn][1], smi[rn][1], mul2(cb2i[rn][1], sre[rn][1]));
            float2 a = upk(e0), b = upk(e1);
            *(float4*)&Er[n*68 + 4*tx] = make_float4(a.x, a.y, b.x, b.y);
            a = upk(f0); b = upk(f1);
            *(float4*)&Ei[n*68 + 4*tx] = make_float4(a.x, a.y, b.x, b.y);
        }
        __syncthreads();
        // Z[n,c] = sum_p dA^{63-p} * U[p,c]
        u64_t zr[2][2] = {0ULL,0ULL,0ULL,0ULL}, zi[2][2] = {0ULL,0ULL,0ULL,0ULL};
        #pragma unroll 4
        for (int p = 0; p < 64; p++){
            float4 u = *(const float4*)&Us[p*68 + 4*tx];
            u64_t u0 = pk2(u.x, u.y), u1 = pk2(u.z, u.w);
            int row = (63-p)*68;
            u64_t wr0 = pks(spr[row + n0]), wr1 = pks(spr[row + n1]);
            u64_t wi0 = pks(spi[row + n0]), wi1 = pks(spi[row + n1]);
            zr[0][0] = fma2(wr0,u0,zr[0][0]); zr[0][1] = fma2(wr0,u1,zr[0][1]);
            zr[1][0] = fma2(wr1,u0,zr[1][0]); zr[1][1] = fma2(wr1,u1,zr[1][1]);
            zi[0][0] = fma2(wi0,u0,zi[0][0]); zi[0][1] = fma2(wi0,u1,zi[0][1]);
            zi[1][0] = fma2(wi1,u0,zi[1][0]); zi[1][1] = fma2(wi1,u1,zi[1][1]);
        }
        // S = dA^64 * S + Z
        #pragma unroll
        for (int rn = 0; rn < 2; rn++)
            #pragma unroll
            for (int q = 0; q < 2; q++){
                u64_t nr = fma2(pa64r[rn], sre[rn][q], fma2(na64i[rn], smi[rn][q], zr[rn][q]));
                u64_t ni = fma2(pa64r[rn], smi[rn][q], fma2(pa64i[rn], sre[rn][q], zi[rn][q]));
                sre[rn][q] = nr; smi[rn][q] = ni;
            }
        // Y = corr + FIR + skip
        u64_t accA[2][2] = {0ULL,0ULL,0ULL,0ULL}, accB[2][2] = {0ULL,0ULL,0ULL,0ULL};
        int rw0 = (ty+1)*68, rw1 = (ty+33)*68;
        #pragma unroll 4
        for (int n = 0; n < 64; n++){
            float4 e = *(const float4*)&Er[n*68 + 4*tx];
            float4 f = *(const float4*)&Ei[n*68 + 4*tx];
            u64_t e0 = pk2(e.x,e.y), e1 = pk2(e.z,e.w);
            u64_t f0 = pk2(f.x,f.y), f1 = pk2(f.z,f.w);
            u64_t wr0 = pks(spr[rw0 + n]), wr1 = pks(spr[rw1 + n]);
            u64_t wi0 = pks(spi[rw0 + n]), wi1 = pks(spi[rw1 + n]);
            accA[0][0] = fma2(wr0,e0,accA[0][0]); accA[0][1] = fma2(wr0,e1,accA[0][1]);
            accA[1][0] = fma2(wr1,e0,accA[1][0]); accA[1][1] = fma2(wr1,e1,accA[1][1]);
            accB[0][0] = fma2(wi0,f0,accB[0][0]); accB[0][1] = fma2(wi0,f1,accB[0][1]);
            accB[1][0] = fma2(wi1,f0,accB[1][0]); accB[1][1] = fma2(wi1,f1,accB[1][1]);
        }
        int p0 = ty, p1 = ty + 32;
        #pragma unroll 2
        for (int tau = 0; tau < 64; tau++){
            float4 kdv = *(const float4*)&Kd[tau*68 + 4*tx];
            u64_t k0 = pk2(kdv.x,kdv.y), k1 = pk2(kdv.z,kdv.w);
            if (tau <= p0){
                float4 u = *(const float4*)&Us[(p0-tau)*68 + 4*tx];
                accA[0][0] = fma2(k0, pk2(u.x,u.y), accA[0][0]);
                accA[0][1] = fma2(k1, pk2(u.z,u.w), accA[0][1]);
            }
            if (tau <= p1){
                float4 u = *(const float4*)&Us[(p1-tau)*68 + 4*tx];
                accA[1][0] = fma2(k0, pk2(u.x,u.y), accA[1][0]);
                accA[1][1] = fma2(k1, pk2(u.z,u.w), accA[1][1]);
            }
        }
        #pragma unroll
        for (int r = 0; r < 2; r++){
            int p = ty + 32*r;
            float4 u = *(const float4*)&Us[p*68 + 4*tx];
            accA[r][0] = fma2(dd0, pk2(u.x,u.y), accA[r][0]);
            accA[r][1] = fma2(dd1, pk2(u.z,u.w), accA[r][1]);
            float2 a0 = upk(accA[r][0]), b0 = upk(accB[r][0]);
            float2 a1 = upk(accA[r][1]), b1 = upk(accB[r][1]);
            *(float4*)&g_Y[(size_t)(tbase+p)*CD + c0 + 4*tx] =
                make_float4(a0.x-b0.x, a0.y-b0.y, a1.x-b1.x, a1.y-b1.y);
        }
    }
}

// ------------------- O[t,h,j] = sum_i Q[t,h,i]*Y[t, h*4096+i*64+j] -------------------
__global__ void k_o(){
    int t = blockIdx.x;
    int tid = threadIdx.x;   // 512
    int h = tid >> 6, j = tid & 63;
    __shared__ float qs[512];
    qs[tid] = g_Q[t*D_ + tid];
    __syncthreads();
    float acc = 0.f;
    const float* Yr = g_Y + (size_t)t*CD + h*4096 + j;
    #pragma unroll 8
    for (int i = 0; i < 64; i++)
        acc += qs[h*64 + i]*Yr[i*64];
    g_O1[t*D_ + tid] = acc;
}

// ------------------- launch -------------------
extern "C" void kernel_launch(void* const* d_in, const int* in_sizes, int n_in,
                              void* d_out, int out_size){
    const float* x  = (const float*)d_in[0];
    const float* WQ = (const float*)d_in[1];
    const float* WK = (const float*)d_in[2];
    const float* WV = (const float*)d_in[3];
    const float* WO = (const float*)d_in[4];
    const float* Cs = (const float*)d_in[5];
    const float* Ds = (const float*)d_in[6];
    const float* Ar = (const float*)d_in[7];
    const float* Ai = (const float*)d_in[8];
    const float* Cr = (const float*)d_in[9];
    const float* Ci = (const float*)d_in[10];
    const float* Dd = (const float*)d_in[11];
    float* out = (float*)d_out;

    float *pO1;
    cudaGetSymbolAddress((void**)&pO1, g_O1);

    const int BIG_SMEM = 26248*4;
    cudaFuncSetAttribute(k_big, cudaFuncAttributeMaxDynamicSharedMemorySize, BIG_SMEM);

    k_tables<<<1, 64>>>(Ar, Ai);
    k_cst<<<D_/64, 256>>>(Cs);
    k_qkv<<<dim3(D_/64, S_/64, 3), 256>>>(x, WQ, WK, WV);
    k_shift<<<(S_*D_)/256, 256>>>(Ds);
    k_cb<<<CD/64, 256>>>(Cr, Ci);
    k_kds<<<CD/256, 256>>>();
    k_big<<<CD/64, 512, BIG_SMEM>>>(Dd);
    k_o<<<S_, 512>>>();
    k_gemm<<<dim3(D_/64, S_/64), 256>>>(pO1, WO, out, S_, D_, D_);
}

// round 15
// speedup vs baseline: 2.7267x; 1.2360x over previous
#include <cuda_runtime.h>

#define S_  1024
#define D_  512
#define CD  32768
#define NST 64
#define GCH 16

typedef unsigned long long u64_t;

__device__ __forceinline__ u64_t fma2(u64_t a, u64_t b, u64_t c){
    u64_t d; asm("fma.rn.f32x2 %0, %1, %2, %3;" : "=l"(d) : "l"(a), "l"(b), "l"(c)); return d;
}
__device__ __forceinline__ u64_t mul2(u64_t a, u64_t b){
    u64_t d; asm("mul.rn.f32x2 %0, %1, %2;" : "=l"(d) : "l"(a), "l"(b)); return d;
}
__device__ __forceinline__ u64_t pk2(float lo, float hi){
    u64_t r; asm("mov.b64 %0, {%1, %2};" : "=l"(r) : "f"(lo), "f"(hi)); return r;
}
__device__ __forceinline__ u64_t pks(float s){ return pk2(s, s); }
__device__ __forceinline__ float2 upk(u64_t a){
    float2 f; asm("mov.b64 {%0, %1}, %2;" : "=f"(f.x), "=f"(f.y) : "l"(a)); return f;
}

__device__ float g_Q[S_*D_];
__device__ float g_K0[S_*D_];
__device__ float g_K[S_*D_];
__device__ float g_V[S_*D_];
__device__ float g_O1[S_*D_];
__device__ float g_CsT[64*D_];
__device__ float g_dBre[NST], g_dBim[NST];
__device__ float g_pwre[65*NST];   // dA^p, [p][n]
__device__ float g_pwim[65*NST];
__device__ float g_CBre[NST*CD];   // [n][c]
__device__ float g_CBim[NST*CD];
__device__ float g_Kds[16*CD];     // 16 taps only
__device__ float g_Y[S_*CD];

__global__ void k_tables(const float* __restrict__ A_re, const float* __restrict__ A_im){
    int n = threadIdx.x;
    if (n >= NST) return;
    double ar = (double)A_re[n], ai = (double)A_im[n];
    double hr = 1.0 + 0.05*ar, hi = 0.05*ai;
    double gr = 1.0 - 0.05*ar, gi = -0.05*ai;
    double den = gr*gr + gi*gi;
    double dAr = (hr*gr + hi*gi)/den, dAi = (hi*gr - hr*gi)/den;
    g_dBre[n] = (float)( 0.1*gr/den);
    g_dBim[n] = (float)(-0.1*gi/den);
    double pr = 1.0, pi = 0.0;
    for (int p = 0; p <= 64; p++){
        g_pwre[p*NST + n] = (float)pr;
        g_pwim[p*NST + n] = (float)pi;
        double nr = pr*dAr - pi*dAi, ni = pr*dAi + pi*dAr;
        pr = nr; pi = ni;
    }
}

__global__ void __launch_bounds__(256) k_cst(const float* __restrict__ Cs){
    __shared__ float t[64][65];
    int d0 = blockIdx.x*64, tid = threadIdx.x;
    for (int i = tid; i < 4096; i += 256){
        int dd = i >> 6, j = i & 63;
        t[dd][j] = Cs[(d0+dd)*64 + j];
    }
    __syncthreads();
    for (int i = tid; i < 4096; i += 256){
        int j = i >> 6, dd = i & 63;
        g_CsT[j*D_ + d0 + dd] = t[dd][j];
    }
}

// CB build + transpose + 16-tap Kds, one kernel
__global__ void __launch_bounds__(256) k_cbkds(const float* __restrict__ Cr, const float* __restrict__ Ci){
    __shared__ float tr[64][65], ti[64][65];
    __shared__ float spr16[1024], spi16[1024];
    __shared__ float dbr[64], dbi[64];
    int c0 = blockIdx.x*64, tid = threadIdx.x;
    if (tid < 64){ dbr[tid] = g_dBre[tid]; dbi[tid] = g_dBim[tid]; }
    for (int i = tid; i < 1024; i += 256){ spr16[i] = g_pwre[i]; spi16[i] = g_pwim[i]; }
    __syncthreads();
    for (int i = tid; i < 4096; i += 256){
        int cc = i >> 6, nn = i & 63;
        float a = Cr[(size_t)(c0+cc)*64 + nn], b = Ci[(size_t)(c0+cc)*64 + nn];
        tr[cc][nn] = a*dbr[nn] - b*dbi[nn];
        ti[cc][nn] = a*dbi[nn] + b*dbr[nn];
    }
    __syncthreads();
    for (int i = tid; i < 4096; i += 256){
        int nn = i >> 6, cc = i & 63;
        g_CBre[(size_t)nn*CD + c0 + cc] = tr[cc][nn];
        g_CBim[(size_t)nn*CD + c0 + cc] = ti[cc][nn];
    }
    int cc = tid & 63, t0 = (tid >> 6)*4;
    float acc[4] = {0.f,0.f,0.f,0.f};
    for (int n = 0; n < 64; n++){
        float a = tr[cc][n], b = ti[cc][n];
        #pragma unroll
        for (int m = 0; m < 4; m++)
            acc[m] += a*spr16[(t0+m)*64 + n] - b*spi16[(t0+m)*64 + n];
    }
    #pragma unroll
    for (int m = 0; m < 4; m++)
        g_Kds[(size_t)(t0+m)*CD + c0 + cc] = 2.f*acc[m];
}

// QKV projections, 32x64 tiles
__global__ void __launch_bounds__(256) k_qkv32(const float* __restrict__ x,
        const float* __restrict__ WQ, const float* __restrict__ WK, const float* __restrict__ WV){
    const float* B = blockIdx.z == 0 ? WQ : (blockIdx.z == 1 ? WK : WV);
    float* C = blockIdx.z == 0 ? g_Q : (blockIdx.z == 1 ? g_K0 : g_V);
    __shared__ float As[16][33], Bs[16][65];
    int m0 = blockIdx.y*32, n0 = blockIdx.x*64;
    int tid = threadIdx.x, tx = tid & 15, ty = tid >> 4;
    float acc[2][4];
    #pragma unroll
    for (int i = 0; i < 2; i++)
        #pragma unroll
        for (int j = 0; j < 4; j++) acc[i][j] = 0.f;
    for (int k0 = 0; k0 < D_; k0 += 16){
        int lr = tid >> 2, lc = (tid & 3)*4;
        if (tid < 128){
            float4 av = *(const float4*)&x[(m0+lr)*D_ + k0 + lc];
            As[lc+0][lr] = av.x; As[lc+1][lr] = av.y; As[lc+2][lr] = av.z; As[lc+3][lr] = av.w;
        }
        float4 bv = *(const float4*)&B[(n0+lr)*D_ + k0 + lc];
        Bs[lc+0][lr] = bv.x; Bs[lc+1][lr] = bv.y; Bs[lc+2][lr] = bv.z; Bs[lc+3][lr] = bv.w;
        __syncthreads();
        #pragma unroll
        for (int kk = 0; kk < 16; kk++){
            float a0 = As[kk][ty], a1 = As[kk][ty+16], b[4];
            #pragma unroll
            for (int j = 0; j < 4; j++) b[j] = Bs[kk][tx + 16*j];
            #pragma unroll
            for (int j = 0; j < 4; j++){ acc[0][j] += a0*b[j]; acc[1][j] += a1*b[j]; }
        }
        __syncthreads();
    }
    #pragma unroll
    for (int i = 0; i < 2; i++)
        #pragma unroll
        for (int j = 0; j < 4; j++)
            C[(m0+ty+16*i)*D_ + n0+tx+16*j] = acc[i][j];
}

__global__ void __launch_bounds__(256) k_gemm32(const float* __restrict__ A,
        const float* __restrict__ B, float* __restrict__ C, int M, int N, int K){
    __shared__ float As[16][33], Bs[16][65];
    int m0 = blockIdx.y*32, n0 = blockIdx.x*64;
    int tid = threadIdx.x, tx = tid & 15, ty = tid >> 4;
    float acc[2][4];
    #pragma unroll
    for (int i = 0; i < 2; i++)
        #pragma unroll
        for (int j = 0; j < 4; j++) acc[i][j] = 0.f;
    for (int k0 = 0; k0 < K; k0 += 16){
        int lr = tid >> 2, lc = (tid & 3)*4;
        if (tid < 128){
            float4 av = *(const float4*)&A[(m0+lr)*K + k0 + lc];
            As[lc+0][lr] = av.x; As[lc+1][lr] = av.y; As[lc+2][lr] = av.z; As[lc+3][lr] = av.w;
        }
        float4 bv = *(const float4*)&B[(n0+lr)*K + k0 + lc];
        Bs[lc+0][lr] = bv.x; Bs[lc+1][lr] = bv.y; Bs[lc+2][lr] = bv.z; Bs[lc+3][lr] = bv.w;
        __syncthreads();
        #pragma unroll
        for (int kk = 0; kk < 16; kk++){
            float a0 = As[kk][ty], a1 = As[kk][ty+16], b[4];
            #pragma unroll
            for (int j = 0; j < 4; j++) b[j] = Bs[kk][tx + 16*j];
            #pragma unroll
            for (int j = 0; j < 4; j++){ acc[0][j] += a0*b[j]; acc[1][j] += a1*b[j]; }
        }
        __syncthreads();
    }
    #pragma unroll
    for (int i = 0; i < 2; i++)
        #pragma unroll
        for (int j = 0; j < 4; j++)
            C[(m0+ty+16*i)*N + n0+tx+16*j] = acc[i][j];
}

__global__ void k_shift(const float* __restrict__ Ds){
    int idx = blockIdx.x*256 + threadIdx.x;
    int d = idx & (D_-1), t = idx >> 9;
    float acc = Ds[d]*g_K0[t*D_ + d];
    int jm = t < 63 ? t : 63;
    for (int j = 0; j <= jm; j++)
        acc += g_CsT[j*D_ + d]*g_K0[(t-j)*D_ + d];
    g_K[idx] = acc;
}

// ============ fused SSM core, 16-wide sub-chunks ============
#define EBANK 4352
__global__ void __launch_bounds__(512) k_big(const float* __restrict__ Dd){
    extern __shared__ float sm[];
    u64_t* WR2 = (u64_t*)sm;                 // [17][64] dup
    u64_t* WI2 = (u64_t*)(sm + 2176);
    u64_t* WCr = (u64_t*)(sm + 4352);        // [64][18] n-major dup
    u64_t* WCi = (u64_t*)(sm + 6656);
    float* Us  = sm + 8960;                  // [64][68]
    float* Kd  = sm + 13312;                 // [16][68]
    float* Er  = sm + 14400;                 // [4][64][68]
    float* Ei  = sm + 31808;
    int bx = blockIdx.x;
    int c0 = bx*64, vb = (bx >> 6)*64;
    int tid = threadIdx.x, tx = tid & 15, ty = tid >> 4;
    int n0_ = ty, n1_ = ty + 32;
    int qsub = ty >> 3, rr = ty & 7;
    u64_t negone = pks(-1.f);

    for (int i = tid; i < 1088; i += 512){
        WR2[i] = pks(g_pwre[i]);
        WI2[i] = pks(g_pwim[i]);
    }
    for (int i = tid; i < 1152; i += 512){
        int n = i/18, e = i - n*18;
        float vr = (e < 17) ? g_pwre[e*64 + n] : 0.f;
        float vi = (e < 17) ? g_pwim[e*64 + n] : 0.f;
        WCr[i] = pks(vr); WCi[i] = pks(vi);
    }
    for (int i = tid; i < 1024; i += 512){
        int r = i >> 6, c = i & 63;
        Kd[r*68 + c] = g_Kds[(size_t)r*CD + c0 + c];
    }
    u64_t cb2r[2][2], cb2i[2][2], ncb2i[2][2], pa16r[2], pa16i[2], na16i[2];
    #pragma unroll
    for (int rn = 0; rn < 2; rn++){
        int n = ty + 32*rn;
        #pragma unroll
        for (int q = 0; q < 2; q++){
            float2 cr = *(const float2*)&g_CBre[(size_t)n*CD + c0 + 4*tx + 2*q];
            float2 ci = *(const float2*)&g_CBim[(size_t)n*CD + c0 + 4*tx + 2*q];
            cb2r[rn][q]  = pk2(2.f*cr.x, 2.f*cr.y);
            cb2i[rn][q]  = pk2(2.f*ci.x, 2.f*ci.y);
            ncb2i[rn][q] = pk2(-2.f*ci.x, -2.f*ci.y);
        }
        pa16r[rn] = pks(g_pwre[16*64 + n]);
        pa16i[rn] = pks(g_pwim[16*64 + n]);
        na16i[rn] = mul2(negone, pa16i[rn]);
    }
    float4 dv = *(const float4*)&Dd[c0 + 4*tx];
    u64_t dd0 = pk2(dv.x, dv.y), dd1 = pk2(dv.z, dv.w);
    u64_t sre[2][2] = {0ULL,0ULL,0ULL,0ULL}, smi[2][2] = {0ULL,0ULL,0ULL,0ULL};

    #pragma unroll 1
    for (int g = 0; g < GCH; g++){
        int tbase = g*64;
        __syncthreads();
        for (int i = tid; i < 1024; i += 512){
            int r = i >> 4, c4 = (i & 15)*4;
            float kv = g_K[(size_t)(tbase+r)*D_ + bx];
            float4 v = *(const float4*)&g_V[(size_t)(tbase+r)*D_ + vb + c4];
            *(float4*)&Us[r*68 + c4] = make_float4(kv*v.x, kv*v.y, kv*v.z, kv*v.w);
        }
        __syncthreads();
        // ---- scan over 4 sub-chunks ----
        #pragma unroll
        for (int q = 0; q < 4; q++){
            #pragma unroll
            for (int rn = 0; rn < 2; rn++){
                int n = ty + 32*rn;
                u64_t e0 = fma2(cb2r[rn][0], sre[rn][0], mul2(ncb2i[rn][0], smi[rn][0]));
                u64_t e1 = fma2(cb2r[rn][1], sre[rn][1], mul2(ncb2i[rn][1], smi[rn][1]));
                u64_t f0 = mul2(negone, fma2(cb2r[rn][0], smi[rn][0], mul2(cb2i[rn][0], sre[rn][0])));
                u64_t f1 = mul2(negone, fma2(cb2r[rn][1], smi[rn][1], mul2(cb2i[rn][1], sre[rn][1])));
                int base = q*EBANK + n*68 + 4*tx;
                float2 a = upk(e0), b = upk(e1);
                *(float4*)&Er[base] = make_float4(a.x, a.y, b.x, b.y);
                a = upk(f0); b = upk(f1);
                *(float4*)&Ei[base] = make_float4(a.x, a.y, b.x, b.y);
            }
            u64_t zr[2][2] = {0ULL,0ULL,0ULL,0ULL}, zi[2][2] = {0ULL,0ULL,0ULL,0ULL};
            #pragma unroll 4
            for (int r = 0; r < 16; r++){
                float4 u = *(const float4*)&Us[(q*16+r)*68 + 4*tx];
                u64_t u0 = pk2(u.x, u.y), u1 = pk2(u.z, u.w);
                int e = (15 - r)*64;
                u64_t wr0 = WR2[e + n0_], wr1 = WR2[e + n1_];
                u64_t wi0 = WI2[e + n0_], wi1 = WI2[e + n1_];
                zr[0][0] = fma2(wr0,u0,zr[0][0]); zr[0][1] = fma2(wr0,u1,zr[0][1]);
                zr[1][0] = fma2(wr1,u0,zr[1][0]); zr[1][1] = fma2(wr1,u1,zr[1][1]);
                zi[0][0] = fma2(wi0,u0,zi[0][0]); zi[0][1] = fma2(wi0,u1,zi[0][1]);
                zi[1][0] = fma2(wi1,u0,zi[1][0]); zi[1][1] = fma2(wi1,u1,zi[1][1]);
            }
            #pragma unroll
            for (int rn = 0; rn < 2; rn++)
                #pragma unroll
                for (int p2 = 0; p2 < 2; p2++){
                    u64_t nr = fma2(pa16r[rn], sre[rn][p2], fma2(na16i[rn], smi[rn][p2], zr[rn][p2]));
                    u64_t ni = fma2(pa16r[rn], smi[rn][p2], fma2(pa16i[rn], sre[rn][p2], zi[rn][p2]));
                    sre[rn][p2] = nr; smi[rn][p2] = ni;
                }
        }
        __syncthreads();
        // ---- corr + FIR + skip (rows p0, p1 within sub qsub) ----
        int p0 = qsub*16 + rr, p1 = p0 + 8;
        int eb = qsub*EBANK;
        u64_t acc0[2] = {0ULL,0ULL}, acc1[2] = {0ULL,0ULL};
        #pragma unroll 4
        for (int n = 0; n < 64; n++){
            float4 e = *(const float4*)&Er[eb + n*68 + 4*tx];
            float4 f = *(const float4*)&Ei[eb + n*68 + 4*tx];
            u64_t e0 = pk2(e.x,e.y), e1 = pk2(e.z,e.w);
            u64_t f0 = pk2(f.x,f.y), f1 = pk2(f.z,f.w);
            int wb = n*18;
            u64_t wr0 = WCr[wb + rr + 1], wi0 = WCi[wb + rr + 1];
            u64_t wr1 = WCr[wb + rr + 9], wi1 = WCi[wb + rr + 9];
            acc0[0] = fma2(wr0, e0, acc0[0]); acc0[0] = fma2(wi0, f0, acc0[0]);
            acc0[1] = fma2(wr0, e1, acc0[1]); acc0[1] = fma2(wi0, f1, acc0[1]);
            acc1[0] = fma2(wr1, e0, acc1[0]); acc1[0] = fma2(wi1, f0, acc1[0]);
            acc1[1] = fma2(wr1, e1, acc1[1]); acc1[1] = fma2(wi1, f1, acc1[1]);
        }
        #pragma unroll 4
        for (int tau = 0; tau < 16; tau++){
            float4 kdv = *(const float4*)&Kd[tau*68 + 4*tx];
            u64_t k0 = pk2(kdv.x, kdv.y), k1 = pk2(kdv.z, kdv.w);
            if (tau <= rr){
                float4 u = *(const float4*)&Us[(p0-tau)*68 + 4*tx];
                acc0[0] = fma2(k0, pk2(u.x,u.y), acc0[0]);
                acc0[1] = fma2(k1, pk2(u.z,u.w), acc0[1]);
            }
            if (tau <= rr + 8){
                float4 u = *(const float4*)&Us[(p1-tau)*68 + 4*tx];
                acc1[0] = fma2(k0, pk2(u.x,u.y), acc1[0]);
                acc1[1] = fma2(k1, pk2(u.z,u.w), acc1[1]);
            }
        }
        {
            float4 u = *(const float4*)&Us[p0*68 + 4*tx];
            acc0[0] = fma2(dd0, pk2(u.x,u.y), acc0[0]);
            acc0[1] = fma2(dd1, pk2(u.z,u.w), acc0[1]);
            float2 a = upk(acc0[0]), b = upk(acc0[1]);
            *(float4*)&g_Y[(size_t)(tbase+p0)*CD + c0 + 4*tx] = make_float4(a.x, a.y, b.x, b.y);
            u = *(const float4*)&Us[p1*68 + 4*tx];
            acc1[0] = fma2(dd0, pk2(u.x,u.y), acc1[0]);
            acc1[1] = fma2(dd1, pk2(u.z,u.w), acc1[1]);
            a = upk(acc1[0]); b = upk(acc1[1]);
            *(float4*)&g_Y[(size_t)(tbase+p1)*CD + c0 + 4*tx] = make_float4(a.x, a.y, b.x, b.y);
        }
    }
}

__global__ void k_o(){
    int t = blockIdx.x, tid = threadIdx.x;
    int h = tid >> 6;
    __shared__ float qs[512];
    qs[tid] = g_Q[t*D_ + tid];
    __syncthreads();
    float acc = 0.f;
    const float* Yr = g_Y + (size_t)t*CD + h*4096 + (tid & 63);
    #pragma unroll 8
    for (int i = 0; i < 64; i++)
        acc += qs[h*64 + i]*Yr[i*64];
    g_O1[t*D_ + tid] = acc;
}

extern "C" void kernel_launch(void* const* d_in, const int* in_sizes, int n_in,
                              void* d_out, int out_size){
    const float* x  = (const float*)d_in[0];
    const float* WQ = (const float*)d_in[1];
    const float* WK = (const float*)d_in[2];
    const float* WV = (const float*)d_in[3];
    const float* WO = (const float*)d_in[4];
    const float* Cs = (const float*)d_in[5];
    const float* Ds = (const float*)d_in[6];
    const float* Ar = (const float*)d_in[7];
    const float* Ai = (const float*)d_in[8];
    const float* Cr = (const float*)d_in[9];
    const float* Ci = (const float*)d_in[10];
    const float* Dd = (const float*)d_in[11];
    float* out = (float*)d_out;

    float* pO1;
    cudaGetSymbolAddress((void**)&pO1, g_O1);

    const int BIG_SMEM = 49216*4;
    cudaFuncSetAttribute(k_big, cudaFuncAttributeMaxDynamicSharedMemorySize, BIG_SMEM);

    k_tables<<<1, 64>>>(Ar, Ai);
    k_cst<<<D_/64, 256>>>(Cs);
    k_qkv32<<<dim3(D_/64, S_/32, 3), 256>>>(x, WQ, WK, WV);
    k_shift<<<(S_*D_)/256, 256>>>(Ds);
    k_cbkds<<<CD/64, 256>>>(Cr, Ci);
    k_big<<<CD/64, 512, BIG_SMEM>>>(Dd);
    k_o<<<S_, 512>>>();
    k_gemm32<<<dim3(D_/64, S_/32), 256>>>(pO1, WO, out, S_, D_, D_);
}